// round 2
// baseline (speedup 1.0000x reference)
#include <cuda_runtime.h>
#include <cuda_bf16.h>
#include <math.h>

// Problem dims (fixed per reference)
#define ED   1024
#define GH   1024
#define NL   3
#define NH   8
#define HD   128
#define NN_  2048   // graph nodes
#define BB   1024   // batch

// ---------------- scratch (static device globals; no allocation) ----------------
__device__ float g_x [NN_*GH];
__device__ float g_Wl[ED*GH];
__device__ float g_Wh[NN_*GH];
__device__ float g_s1[NN_*NH];
__device__ float g_s2[NN_*NH];
__device__ float g_h [NN_*GH];
__device__ float g_G [NN_*ED];
__device__ float g_LG[NN_*ED];
__device__ float g_t1[BB*ED];
__device__ float g_t2[BB*ED];
__device__ float g_q [BB*ED];
__device__ float g_p [BB*ED];
__device__ float g_neg[BB*BB];
__device__ float g_infoRow[BB];
__device__ float g_lapRow[NN_];
__device__ int   g_deg[NN_];
__device__ int   g_rowptr[NN_+1];
__device__ int   g_colidx[NN_*NN_];

// ---------------- block reduction helpers (blockDim == 256) ----------------
__device__ __forceinline__ float blk_sum256(float v, float* red8) {
    int tid = threadIdx.x, lane = tid & 31, w = tid >> 5;
    #pragma unroll
    for (int o = 16; o; o >>= 1) v += __shfl_xor_sync(0xffffffffu, v, o);
    __syncthreads();
    if (lane == 0) red8[w] = v;
    __syncthreads();
    if (tid == 0) { float t = 0.f; for (int k = 0; k < 8; k++) t += red8[k]; red8[0] = t; }
    __syncthreads();
    return red8[0];
}

__device__ __forceinline__ float blk_max256(float v, float* red8) {
    int tid = threadIdx.x, lane = tid & 31, w = tid >> 5;
    #pragma unroll
    for (int o = 16; o; o >>= 1) v = fmaxf(v, __shfl_xor_sync(0xffffffffu, v, o));
    __syncthreads();
    if (lane == 0) red8[w] = v;
    __syncthreads();
    if (tid == 0) { float t = red8[0]; for (int k = 1; k < 8; k++) t = fmaxf(t, red8[k]); red8[0] = t; }
    __syncthreads();
    return red8[0];
}

// ---------------- SGEMM: C[M,N] = A[M,K] @ B + (bias) ----------------
// 128x128 tile, BK=16, 256 threads, 8x8 per-thread. All dims multiples of 128/16.
__global__ void __launch_bounds__(256) sgemm_nn(
    const float* __restrict__ A, const float* __restrict__ B,
    const float* __restrict__ bias, float* __restrict__ C,
    int M, int N, int K)
{
    __shared__ float As[16][128];
    __shared__ float Bs[16][128];
    const int tid = threadIdx.x;
    const int bm = blockIdx.y * 128, bn = blockIdx.x * 128;
    const int ty = tid >> 4, tx = tid & 15;
    const int a_row = tid >> 1, a_kg = (tid & 1) * 8;
    const int b_kr = tid >> 4,  b_cg = (tid & 15) * 8;

    float acc[8][8];
    #pragma unroll
    for (int i = 0; i < 8; i++)
        #pragma unroll
        for (int j = 0; j < 8; j++) acc[i][j] = 0.f;

    const float* Aptr = A + (size_t)(bm + a_row) * K + a_kg;

    for (int k0 = 0; k0 < K; k0 += 16) {
        float4 a0 = *(const float4*)(Aptr + k0);
        float4 a1 = *(const float4*)(Aptr + k0 + 4);
        As[a_kg+0][a_row] = a0.x; As[a_kg+1][a_row] = a0.y;
        As[a_kg+2][a_row] = a0.z; As[a_kg+3][a_row] = a0.w;
        As[a_kg+4][a_row] = a1.x; As[a_kg+5][a_row] = a1.y;
        As[a_kg+6][a_row] = a1.z; As[a_kg+7][a_row] = a1.w;

        const float* Bp = B + (size_t)(k0 + b_kr) * N + bn + b_cg;
        float4 b0 = *(const float4*)Bp;
        float4 b1 = *(const float4*)(Bp + 4);
        *(float4*)&Bs[b_kr][b_cg]     = b0;
        *(float4*)&Bs[b_kr][b_cg + 4] = b1;
        __syncthreads();

        #pragma unroll
        for (int kk = 0; kk < 16; kk++) {
            float ar[8], br[8];
            *(float4*)(ar)     = *(const float4*)&As[kk][ty*8];
            *(float4*)(ar + 4) = *(const float4*)&As[kk][ty*8 + 4];
            *(float4*)(br)     = *(const float4*)&Bs[kk][tx*8];
            *(float4*)(br + 4) = *(const float4*)&Bs[kk][tx*8 + 4];
            #pragma unroll
            for (int i = 0; i < 8; i++)
                #pragma unroll
                for (int j = 0; j < 8; j++) acc[i][j] += ar[i] * br[j];
        }
        __syncthreads();
    }

    #pragma unroll
    for (int i = 0; i < 8; i++) {
        int r = bm + ty*8 + i;
        float* Cp = C + (size_t)r * N + bn + tx*8;
        float bsum[8];
        #pragma unroll
        for (int j = 0; j < 8; j++)
            bsum[j] = acc[i][j] + (bias ? __ldg(&bias[bn + tx*8 + j]) : 0.f);
        *(float4*)(Cp)     = make_float4(bsum[0], bsum[1], bsum[2], bsum[3]);
        *(float4*)(Cp + 4) = make_float4(bsum[4], bsum[5], bsum[6], bsum[7]);
    }
}

// C[M,N] = A[M,K] @ B^T, B stored [N,K] row-major
__global__ void __launch_bounds__(256) sgemm_nt(
    const float* __restrict__ A, const float* __restrict__ B,
    float* __restrict__ C, int M, int N, int K)
{
    __shared__ float As[16][128];
    __shared__ float Bs[16][128];
    const int tid = threadIdx.x;
    const int bm = blockIdx.y * 128, bn = blockIdx.x * 128;
    const int ty = tid >> 4, tx = tid & 15;
    const int a_row = tid >> 1, a_kg = (tid & 1) * 8;

    float acc[8][8];
    #pragma unroll
    for (int i = 0; i < 8; i++)
        #pragma unroll
        for (int j = 0; j < 8; j++) acc[i][j] = 0.f;

    const float* Aptr = A + (size_t)(bm + a_row) * K + a_kg;
    const float* Bptr = B + (size_t)(bn + a_row) * K + a_kg;

    for (int k0 = 0; k0 < K; k0 += 16) {
        float4 a0 = *(const float4*)(Aptr + k0);
        float4 a1 = *(const float4*)(Aptr + k0 + 4);
        As[a_kg+0][a_row] = a0.x; As[a_kg+1][a_row] = a0.y;
        As[a_kg+2][a_row] = a0.z; As[a_kg+3][a_row] = a0.w;
        As[a_kg+4][a_row] = a1.x; As[a_kg+5][a_row] = a1.y;
        As[a_kg+6][a_row] = a1.z; As[a_kg+7][a_row] = a1.w;

        float4 b0 = *(const float4*)(Bptr + k0);
        float4 b1 = *(const float4*)(Bptr + k0 + 4);
        Bs[a_kg+0][a_row] = b0.x; Bs[a_kg+1][a_row] = b0.y;
        Bs[a_kg+2][a_row] = b0.z; Bs[a_kg+3][a_row] = b0.w;
        Bs[a_kg+4][a_row] = b1.x; Bs[a_kg+5][a_row] = b1.y;
        Bs[a_kg+6][a_row] = b1.z; Bs[a_kg+7][a_row] = b1.w;
        __syncthreads();

        #pragma unroll
        for (int kk = 0; kk < 16; kk++) {
            float ar[8], br[8];
            *(float4*)(ar)     = *(const float4*)&As[kk][ty*8];
            *(float4*)(ar + 4) = *(const float4*)&As[kk][ty*8 + 4];
            *(float4*)(br)     = *(const float4*)&Bs[kk][tx*8];
            *(float4*)(br + 4) = *(const float4*)&Bs[kk][tx*8 + 4];
            #pragma unroll
            for (int i = 0; i < 8; i++)
                #pragma unroll
                for (int j = 0; j < 8; j++) acc[i][j] += ar[i] * br[j];
        }
        __syncthreads();
    }

    #pragma unroll
    for (int i = 0; i < 8; i++) {
        int r = bm + ty*8 + i;
        float* Cp = C + (size_t)r * N + bn + tx*8;
        *(float4*)(Cp)     = make_float4(acc[i][0], acc[i][1], acc[i][2], acc[i][3]);
        *(float4*)(Cp + 4) = make_float4(acc[i][4], acc[i][5], acc[i][6], acc[i][7]);
    }
}

// ---------------- misc kernels ----------------
__global__ void copy_f4(const float4* __restrict__ src, float4* __restrict__ dst, int n4) {
    int i = blockIdx.x * blockDim.x + threadIdx.x;
    if (i < n4) dst[i] = src[i];
}

__global__ void reorder_gatw(const float* __restrict__ src, float* __restrict__ dst) {
    int idx = blockIdx.x * 256 + threadIdx.x;   // grid covers exactly 1M
    int f = idx >> 10, c = idx & 1023, h = c >> 7, o = c & 127;
    dst[idx] = src[((size_t)h * 1024 + f) * 128 + o];
}

// ---------------- CSR build (adj > 0) ----------------
__global__ void csr_count(const float* __restrict__ adj, int* __restrict__ deg) {
    int w = (blockIdx.x * blockDim.x + threadIdx.x) >> 5;
    int lane = threadIdx.x & 31;
    if (w >= NN_) return;
    const float* row = adj + (size_t)w * NN_;
    int cnt = 0;
    for (int c = 0; c < NN_/32; c++) {
        unsigned m = __ballot_sync(0xffffffffu, row[c*32 + lane] > 0.f);
        cnt += __popc(m);
    }
    if (lane == 0) deg[w] = cnt;
}

__global__ void csr_scan(const int* __restrict__ deg, int* __restrict__ rowptr) {
    __shared__ int ps[128];
    int t = threadIdx.x; // 128
    int s = 0;
    for (int i = 0; i < 16; i++) s += deg[t*16 + i];
    ps[t] = s;
    __syncthreads();
    if (t == 0) { int run = 0; for (int i = 0; i < 128; i++) { int v = ps[i]; ps[i] = run; run += v; } }
    __syncthreads();
    int run = ps[t];
    for (int i = 0; i < 16; i++) { rowptr[t*16 + i] = run; run += deg[t*16 + i]; }
    if (t == 127) rowptr[NN_] = run;
}

__global__ void csr_fill(const float* __restrict__ adj, const int* __restrict__ rowptr,
                         int* __restrict__ colidx) {
    int w = (blockIdx.x * blockDim.x + threadIdx.x) >> 5;
    int lane = threadIdx.x & 31;
    if (w >= NN_) return;
    const float* row = adj + (size_t)w * NN_;
    int base = rowptr[w];
    for (int c = 0; c < NN_/32; c++) {
        int j = c*32 + lane;
        bool p = row[j] > 0.f;
        unsigned m = __ballot_sync(0xffffffffu, p);
        if (p) colidx[base + __popc(m & ((1u << lane) - 1u))] = j;
        base += __popc(m);
    }
}

// ---------------- GAT pieces ----------------
__global__ void gat_scores(const float* __restrict__ Wh, const float* __restrict__ a1,
                           const float* __restrict__ a2, float* __restrict__ s1,
                           float* __restrict__ s2) {
    int n = blockIdx.x;
    int w = threadIdx.x >> 5, lane = threadIdx.x & 31;  // 256 threads = 8 warps = 8 heads
    const float* wr  = Wh + (size_t)n * GH + w * HD;
    const float* a1p = a1 + w * HD;
    const float* a2p = a2 + w * HD;
    float v1 = 0.f, v2 = 0.f;
    for (int o = lane; o < HD; o += 32) { float x = wr[o]; v1 += x * a1p[o]; v2 += x * a2p[o]; }
    #pragma unroll
    for (int o = 16; o; o >>= 1) {
        v1 += __shfl_xor_sync(0xffffffffu, v1, o);
        v2 += __shfl_xor_sync(0xffffffffu, v2, o);
    }
    if (lane == 0) { s1[n*NH + w] = v1; s2[n*NH + w] = v2; }
}

__global__ void __launch_bounds__(256) gat_aggregate(
    const float* __restrict__ Wh, const float* __restrict__ s1,
    const float* __restrict__ s2, const int* __restrict__ rowptr,
    const int* __restrict__ colidx, float* __restrict__ out)
{
    const int i = blockIdx.x, tid = threadIdx.x, lane = tid & 31, w = tid >> 5;
    __shared__ float s1sh[8], mh[8], zh[8];
    __shared__ float wred[8][8];
    __shared__ float att[128*8];
    __shared__ int   jsh[128];

    if (tid < 8) s1sh[tid] = s1[i*NH + tid];
    const int base = rowptr[i];
    const int deg  = rowptr[i+1] - base;
    __syncthreads();

    // pass 1: per-head max over neighbors
    float lm[8];
    #pragma unroll
    for (int h = 0; h < 8; h++) lm[h] = -1e30f;
    for (int jj = tid; jj < deg; jj += 256) {
        int j = colidx[base + jj];
        #pragma unroll
        for (int h = 0; h < 8; h++) {
            float e = s1sh[h] + s2[j*NH + h];
            e = e > 0.f ? e : 0.2f * e;
            lm[h] = fmaxf(lm[h], e);
        }
    }
    #pragma unroll
    for (int h = 0; h < 8; h++) {
        #pragma unroll
        for (int o = 16; o; o >>= 1) lm[h] = fmaxf(lm[h], __shfl_xor_sync(0xffffffffu, lm[h], o));
    }
    if (lane == 0) {
        for (int h = 0; h < 8; h++) wred[w][h] = lm[h];
    }
    __syncthreads();
    if (tid < 8) {
        float m = wred[0][tid];
        for (int ww = 1; ww < 8; ww++) m = fmaxf(m, wred[ww][tid]);
        mh[tid] = m;
    }
    __syncthreads();

    // pass 2: per-head sum of exp
    float ls[8];
    #pragma unroll
    for (int h = 0; h < 8; h++) ls[h] = 0.f;
    for (int jj = tid; jj < deg; jj += 256) {
        int j = colidx[base + jj];
        #pragma unroll
        for (int h = 0; h < 8; h++) {
            float e = s1sh[h] + s2[j*NH + h];
            e = e > 0.f ? e : 0.2f * e;
            ls[h] += expf(e - mh[h]);
        }
    }
    #pragma unroll
    for (int h = 0; h < 8; h++) {
        #pragma unroll
        for (int o = 16; o; o >>= 1) ls[h] += __shfl_xor_sync(0xffffffffu, ls[h], o);
    }
    __syncthreads();
    if (lane == 0) {
        for (int h = 0; h < 8; h++) wred[w][h] = ls[h];
    }
    __syncthreads();
    if (tid < 8) {
        float s = 0.f;
        for (int ww = 0; ww < 8; ww++) s += wred[ww][tid];
        zh[tid] = s;
    }
    __syncthreads();

    // phase B: weighted aggregation, chunked att in smem
    float acc0 = 0.f, acc1 = 0.f, acc2 = 0.f, acc3 = 0.f;
    const int c0 = tid, c1 = tid + 256, c2 = tid + 512, c3 = tid + 768;
    const int h0 = c0 >> 7, h1 = c1 >> 7, h2 = c2 >> 7, h3 = c3 >> 7;
    for (int cs = 0; cs < deg; cs += 128) {
        const int nck = min(128, deg - cs);
        __syncthreads();
        for (int idx = tid; idx < nck; idx += 256) jsh[idx] = colidx[base + cs + idx];
        for (int idx = tid; idx < nck * 8; idx += 256) {
            int jj = idx >> 3, h = idx & 7;
            int j = colidx[base + cs + jj];
            float e = s1sh[h] + s2[j*NH + h];
            e = e > 0.f ? e : 0.2f * e;
            att[idx] = expf(e - mh[h]) / zh[h];
        }
        __syncthreads();
        for (int jj = 0; jj < nck; jj++) {
            const float* wr = Wh + (size_t)jsh[jj] * GH;
            const float* at = att + jj * 8;
            acc0 += at[h0] * wr[c0];
            acc1 += at[h1] * wr[c1];
            acc2 += at[h2] * wr[c2];
            acc3 += at[h3] * wr[c3];
        }
    }
    float* orow = out + (size_t)i * GH;
    orow[c0] = acc0; orow[c1] = acc1; orow[c2] = acc2; orow[c3] = acc3;
}

// ---------------- LN + activation ----------------
// mode 0: out = gelu(LN(X)*g+b)     (overwrite out)
// mode 1: out += elu(LN(X)*g+b)     (residual add)
__global__ void ln_act(const float* __restrict__ X, const float* __restrict__ g,
                       const float* __restrict__ b, float* __restrict__ out, int mode) {
    __shared__ float red8[8];
    int row = blockIdx.x, tid = threadIdx.x; // 256 threads, 1024 cols
    const float* xr = X + (size_t)row * 1024;
    float v[4];
    #pragma unroll
    for (int k = 0; k < 4; k++) v[k] = xr[tid + 256*k];
    float s = v[0] + v[1] + v[2] + v[3];
    s = blk_sum256(s, red8);
    float mu = s * (1.f/1024.f);
    float q = 0.f;
    #pragma unroll
    for (int k = 0; k < 4; k++) { float d = v[k] - mu; q += d * d; }
    q = blk_sum256(q, red8);
    float rstd = rsqrtf(q * (1.f/1024.f) + 1e-5f);
    float* orow = out + (size_t)row * 1024;
    #pragma unroll
    for (int k = 0; k < 4; k++) {
        int c = tid + 256*k;
        float y = (v[k] - mu) * rstd * g[c] + b[c];
        if (mode == 0) {
            orow[c] = y * 0.5f * (1.f + erff(y * 0.70710678118654752f));
        } else {
            float e = y > 0.f ? y : expm1f(y);
            orow[c] += e;
        }
    }
}

__global__ void l2norm_rows(const float* __restrict__ X, float* __restrict__ out) {
    __shared__ float red8[8];
    int row = blockIdx.x, tid = threadIdx.x;
    const float* xr = X + (size_t)row * 1024;
    float v[4];
    #pragma unroll
    for (int k = 0; k < 4; k++) v[k] = xr[tid + 256*k];
    float q = v[0]*v[0] + v[1]*v[1] + v[2]*v[2] + v[3]*v[3];
    q = blk_sum256(q, red8);
    float inv = 1.f / fmaxf(sqrtf(q), 1e-12f);
    float* orow = out + (size_t)row * 1024;
    #pragma unroll
    for (int k = 0; k < 4; k++) orow[tid + 256*k] = v[k] * inv;
}

__global__ void rowdot(const float* __restrict__ A, const float* __restrict__ B,
                       float* __restrict__ out) {
    __shared__ float red8[8];
    int row = blockIdx.x, tid = threadIdx.x;
    const float* ar = A + (size_t)row * 1024;
    const float* br = B + (size_t)row * 1024;
    float s = 0.f;
    #pragma unroll
    for (int k = 0; k < 4; k++) { int c = tid + 256*k; s += ar[c] * br[c]; }
    s = blk_sum256(s, red8);
    if (tid == 0) out[row] = s;
}

// per-row: lse(logits)-pos, with logits = [neg[i,i], neg[i,:]]*(1/TEMP)
__global__ void lse_rows(const float* __restrict__ neg, float* __restrict__ infoRow) {
    __shared__ float red8[8];
    int row = blockIdx.x, tid = threadIdx.x;
    const float* r = neg + (size_t)row * 1024;
    float v[4];
    #pragma unroll
    for (int k = 0; k < 4; k++) v[k] = r[tid + 256*k] * 20.0f;  // 1/TEMP
    float m = fmaxf(fmaxf(v[0], v[1]), fmaxf(v[2], v[3]));
    m = blk_max256(m, red8);
    float s = 0.f;
    #pragma unroll
    for (int k = 0; k < 4; k++) s += expf(v[k] - m);
    s = blk_sum256(s, red8);
    if (tid == 0) {
        float pos = r[row] * 20.0f;
        float lse = m + logf(expf(pos - m) + s);
        infoRow[row] = lse - pos;
    }
}

__global__ void finalize_k(const float* __restrict__ infoRow, const float* __restrict__ lapRow,
                           float* __restrict__ out, int out_size) {
    __shared__ float ri[32], rl[32];
    int tid = threadIdx.x, lane = tid & 31, w = tid >> 5; // 1024 threads
    float vi = infoRow[tid];
    float vl = lapRow[tid] + lapRow[tid + 1024];
    #pragma unroll
    for (int o = 16; o; o >>= 1) {
        vi += __shfl_xor_sync(0xffffffffu, vi, o);
        vl += __shfl_xor_sync(0xffffffffu, vl, o);
    }
    if (lane == 0) { ri[w] = vi; rl[w] = vl; }
    __syncthreads();
    if (tid == 0) {
        float si = 0.f, sl = 0.f;
        for (int k = 0; k < 32; k++) { si += ri[k]; sl += rl[k]; }
        float info = si / 1024.f;
        float lap  = sl / 2048.f;
        float total = info + 0.1f * lap;
        out[0] = total;
        if (out_size > 1) out[1] = info;
        if (out_size > 2) out[2] = lap;
    }
}

// ---------------- host ----------------
extern "C" void kernel_launch(void* const* d_in, const int* in_sizes, int n_in,
                              void* d_out, int out_size) {
    const float* query = (const float*)d_in[0];
    const float* docs  = (const float*)d_in[1];
    const float* nodes = (const float*)d_in[2];
    const float* adj   = (const float*)d_in[3];
    const float* lapl  = (const float*)d_in[4];
    const float* qW1 = (const float*)d_in[5];  const float* qb1 = (const float*)d_in[6];
    const float* qg  = (const float*)d_in[7];  const float* qbt = (const float*)d_in[8];
    const float* qW2 = (const float*)d_in[9];  const float* qb2 = (const float*)d_in[10];
    const float* dW1 = (const float*)d_in[11]; const float* db1 = (const float*)d_in[12];
    const float* dg  = (const float*)d_in[13]; const float* dbt = (const float*)d_in[14];
    const float* dW2 = (const float*)d_in[15]; const float* db2 = (const float*)d_in[16];
    const float* gatW = (const float*)d_in[17];
    const float* a1   = (const float*)d_in[18];
    const float* a2   = (const float*)d_in[19];
    const float* ln_g = (const float*)d_in[20];
    const float* ln_b = (const float*)d_in[21];
    const float* poW  = (const float*)d_in[22];
    const float* pob  = (const float*)d_in[23];

    void* tp;
    float *px, *pWl, *pWh, *ps1, *ps2, *ph, *pG, *pLG, *pt1, *pt2, *pq, *pp, *pneg, *pinfo, *plap;
    int *pdeg, *prowptr, *pcolidx;
    cudaGetSymbolAddress(&tp, g_x);   px  = (float*)tp;
    cudaGetSymbolAddress(&tp, g_Wl);  pWl = (float*)tp;
    cudaGetSymbolAddress(&tp, g_Wh);  pWh = (float*)tp;
    cudaGetSymbolAddress(&tp, g_s1);  ps1 = (float*)tp;
    cudaGetSymbolAddress(&tp, g_s2);  ps2 = (float*)tp;
    cudaGetSymbolAddress(&tp, g_h);   ph  = (float*)tp;
    cudaGetSymbolAddress(&tp, g_G);   pG  = (float*)tp;
    cudaGetSymbolAddress(&tp, g_LG);  pLG = (float*)tp;
    cudaGetSymbolAddress(&tp, g_t1);  pt1 = (float*)tp;
    cudaGetSymbolAddress(&tp, g_t2);  pt2 = (float*)tp;
    cudaGetSymbolAddress(&tp, g_q);   pq  = (float*)tp;
    cudaGetSymbolAddress(&tp, g_p);   pp  = (float*)tp;
    cudaGetSymbolAddress(&tp, g_neg); pneg = (float*)tp;
    cudaGetSymbolAddress(&tp, g_infoRow); pinfo = (float*)tp;
    cudaGetSymbolAddress(&tp, g_lapRow);  plap  = (float*)tp;
    cudaGetSymbolAddress(&tp, g_deg);     pdeg    = (int*)tp;
    cudaGetSymbolAddress(&tp, g_rowptr);  prowptr = (int*)tp;
    cudaGetSymbolAddress(&tp, g_colidx);  pcolidx = (int*)tp;

    // x = node_embeds
    copy_f4<<<(NN_*ED/4 + 255)/256, 256>>>((const float4*)nodes, (float4*)px, NN_*ED/4);

    // CSR of adj (built fresh every launch; deterministic)
    csr_count<<<NN_*32/256, 256>>>(adj, pdeg);
    csr_scan<<<1, 128>>>(pdeg, prowptr);
    csr_fill<<<NN_*32/256, 256>>>(adj, prowptr, pcolidx);

    // GNN layers
    for (int l = 0; l < NL; l++) {
        reorder_gatw<<<(ED*GH)/256, 256>>>(gatW + (size_t)l*NH*ED*HD, pWl);
        sgemm_nn<<<dim3(GH/128, NN_/128), 256>>>(px, pWl, nullptr, pWh, NN_, GH, ED);
        gat_scores<<<NN_, 256>>>(pWh, a1 + l*NH*HD, a2 + l*NH*HD, ps1, ps2);
        gat_aggregate<<<NN_, 256>>>(pWh, ps1, ps2, prowptr, pcolidx, ph);
        ln_act<<<NN_, 256>>>(ph, ln_g + l*GH, ln_b + l*GH, px, 1);
    }

    // graph_embeds, laplacian term
    sgemm_nn<<<dim3(ED/128, NN_/128), 256>>>(px, poW, pob, pG, NN_, ED, GH);
    sgemm_nn<<<dim3(ED/128, NN_/128), 256>>>(lapl, pG, nullptr, pLG, NN_, ED, NN_);
    rowdot<<<NN_, 256>>>(pG, pLG, plap);

    // query MLP -> q
    sgemm_nn<<<dim3(ED/128, BB/128), 256>>>(query, qW1, qb1, pt1, BB, ED, ED);
    ln_act<<<BB, 256>>>(pt1, qg, qbt, pt2, 0);
    sgemm_nn<<<dim3(ED/128, BB/128), 256>>>(pt2, qW2, qb2, pt1, BB, ED, ED);
    l2norm_rows<<<BB, 256>>>(pt1, pq);

    // doc MLP -> p
    sgemm_nn<<<dim3(ED/128, BB/128), 256>>>(docs, dW1, db1, pt1, BB, ED, ED);
    ln_act<<<BB, 256>>>(pt1, dg, dbt, pt2, 0);
    sgemm_nn<<<dim3(ED/128, BB/128), 256>>>(pt2, dW2, db2, pt1, BB, ED, ED);
    l2norm_rows<<<BB, 256>>>(pt1, pp);

    // neg similarity + losses
    sgemm_nt<<<dim3(BB/128, BB/128), 256>>>(pq, pp, pneg, BB, BB, ED);
    lse_rows<<<BB, 256>>>(pneg, pinfo);
    finalize_k<<<1, 1024>>>(pinfo, plap, (float*)d_out, out_size);
}

// round 4
// speedup vs baseline: 1.8162x; 1.8162x over previous
#include <cuda_runtime.h>
#include <cuda_bf16.h>
#include <math.h>

// Problem dims (fixed per reference)
#define ED   1024
#define GH   1024
#define NL   3
#define NH   8
#define HD   128
#define NN_  2048   // graph nodes
#define BB   1024   // batch

// ---------------- scratch (static device globals; no allocation) ----------------
__device__ float g_x [NN_*GH];
__device__ float g_Wl[ED*GH];
__device__ float g_Wh[NN_*GH];
__device__ float g_s1[NN_*NH];
__device__ float g_s2[NN_*NH];
__device__ float g_h [NN_*GH];
__device__ float g_G [NN_*ED];
__device__ float g_LG[NN_*ED];
__device__ float g_t1[BB*ED];
__device__ float g_t2[BB*ED];
__device__ float g_q [BB*ED];
__device__ float g_p [BB*ED];
__device__ float g_neg[BB*BB];
__device__ float g_infoRow[BB];
__device__ float g_lapRow[NN_];
__device__ int   g_deg[NN_];
__device__ int   g_rowptr[NN_+1];
__device__ int   g_colidx[NN_*NN_];

__device__ __forceinline__ unsigned f2tf32(float x) {
    unsigned r; asm("cvt.rna.tf32.f32 %0, %1;" : "=r"(r) : "f"(x)); return r;
}

// ---------------- TF32 tensor-core GEMM via mma.sync ----------------
// C[M,N] = A[M,K] @ B + bias.  TRANSB=0: B is [K,N] row-major. TRANSB=1: B is [N,K].
// 128x128x32 tile, 256 threads (4x2 warps, warp tile 32x64), double-buffered smem.
#define GSMEM_BYTES (2 * 32 * 132 * 4 * 2)

template<int TRANSB>
__global__ void __launch_bounds__(256, 1) gemm_tf32(
    const float* __restrict__ A, const float* __restrict__ B,
    const float* __restrict__ bias, float* __restrict__ C,
    int M, int N, int K)
{
    extern __shared__ unsigned smem_u[];
    unsigned (*As)[32][132] = reinterpret_cast<unsigned(*)[32][132]>(smem_u);
    unsigned (*Bs)[32][132] = reinterpret_cast<unsigned(*)[32][132]>(smem_u + 2*32*132);

    const int tid = threadIdx.x;
    const int w   = tid >> 5, lane = tid & 31;
    const int g   = lane >> 2, tq = lane & 3;
    const int wm  = w & 3, wn = w >> 2;
    const int bm  = blockIdx.y * 128, bn = blockIdx.x * 128;
    const int nck = K >> 5;

    float4 av[4], bv[4];
    float c[2][8][4];
    #pragma unroll
    for (int mt = 0; mt < 2; mt++)
        #pragma unroll
        for (int nt = 0; nt < 8; nt++)
            #pragma unroll
            for (int j = 0; j < 4; j++) c[mt][nt][j] = 0.f;

    for (int ck = 0; ck <= nck; ck++) {
        // ---- issue global loads for chunk ck into regs ----
        if (ck < nck) {
            #pragma unroll
            for (int i = 0; i < 4; i++) {
                int wt = w * 4 + i;
                int c4 = wt & 7;
                int r  = ((wt & 24) << 2) + lane;   // (wt>>3)*32 + lane
                av[i] = *(const float4*)(A + (size_t)(bm + r) * K + ck * 32 + c4 * 4);
            }
            if (TRANSB) {
                #pragma unroll
                for (int i = 0; i < 4; i++) {
                    int wt = w * 4 + i;
                    int c4 = wt & 7;
                    int r  = ((wt & 24) << 2) + lane;
                    bv[i] = *(const float4*)(B + (size_t)(bn + r) * K + ck * 32 + c4 * 4);
                }
            } else {
                #pragma unroll
                for (int i = 0; i < 4; i++) {
                    int idx = tid + 256 * i;
                    int kr = idx >> 5, c4 = idx & 31;
                    bv[i] = *(const float4*)(B + (size_t)(ck * 32 + kr) * N + bn + c4 * 4);
                }
            }
        }

        // ---- compute on previous buffer ----
        if (ck > 0) {
            const int cb = (ck - 1) & 1;
            #pragma unroll
            for (int s = 0; s < 4; s++) {
                unsigned a[2][4], b[8][2];
                const unsigned* A0 = As[cb][s * 8 + tq];
                const unsigned* A4 = As[cb][s * 8 + tq + 4];
                const int am = wm * 32 + g;
                #pragma unroll
                for (int mt = 0; mt < 2; mt++) {
                    a[mt][0] = A0[am + mt * 16];
                    a[mt][1] = A0[am + mt * 16 + 8];
                    a[mt][2] = A4[am + mt * 16];
                    a[mt][3] = A4[am + mt * 16 + 8];
                }
                const unsigned* B0 = Bs[cb][s * 8 + tq];
                const unsigned* B4 = Bs[cb][s * 8 + tq + 4];
                const int bn0 = wn * 64 + g;
                #pragma unroll
                for (int nt = 0; nt < 8; nt++) {
                    b[nt][0] = B0[bn0 + nt * 8];
                    b[nt][1] = B4[bn0 + nt * 8];
                }
                #pragma unroll
                for (int mt = 0; mt < 2; mt++)
                    #pragma unroll
                    for (int nt = 0; nt < 8; nt++)
                        asm volatile(
                            "mma.sync.aligned.m16n8k8.row.col.f32.tf32.tf32.f32 "
                            "{%0,%1,%2,%3}, {%4,%5,%6,%7}, {%8,%9}, {%0,%1,%2,%3};"
                            : "+f"(c[mt][nt][0]), "+f"(c[mt][nt][1]),
                              "+f"(c[mt][nt][2]), "+f"(c[mt][nt][3])
                            : "r"(a[mt][0]), "r"(a[mt][1]), "r"(a[mt][2]), "r"(a[mt][3]),
                              "r"(b[nt][0]), "r"(b[nt][1]));
            }
        }

        // ---- store regs to smem buffer ck&1 ----
        if (ck < nck) {
            const int sb = ck & 1;
            #pragma unroll
            for (int i = 0; i < 4; i++) {
                int wt = w * 4 + i;
                int c4 = wt & 7;
                int r  = ((wt & 24) << 2) + lane;
                As[sb][c4 * 4 + 0][r] = f2tf32(av[i].x);
                As[sb][c4 * 4 + 1][r] = f2tf32(av[i].y);
                As[sb][c4 * 4 + 2][r] = f2tf32(av[i].z);
                As[sb][c4 * 4 + 3][r] = f2tf32(av[i].w);
            }
            if (TRANSB) {
                #pragma unroll
                for (int i = 0; i < 4; i++) {
                    int wt = w * 4 + i;
                    int c4 = wt & 7;
                    int r  = ((wt & 24) << 2) + lane;
                    Bs[sb][c4 * 4 + 0][r] = f2tf32(bv[i].x);
                    Bs[sb][c4 * 4 + 1][r] = f2tf32(bv[i].y);
                    Bs[sb][c4 * 4 + 2][r] = f2tf32(bv[i].z);
                    Bs[sb][c4 * 4 + 3][r] = f2tf32(bv[i].w);
                }
            } else {
                #pragma unroll
                for (int i = 0; i < 4; i++) {
                    int idx = tid + 256 * i;
                    int kr = idx >> 5, c4 = idx & 31;
                    uint4 t = make_uint4(f2tf32(bv[i].x), f2tf32(bv[i].y),
                                         f2tf32(bv[i].z), f2tf32(bv[i].w));
                    *(uint4*)&Bs[sb][kr][c4 * 4] = t;
                }
            }
        }
        __syncthreads();
    }

    // ---- epilogue ----
    #pragma unroll
    for (int mt = 0; mt < 2; mt++) {
        int row = bm + wm * 32 + mt * 16 + g;
        #pragma unroll
        for (int nt = 0; nt < 8; nt++) {
            int col = bn + wn * 64 + nt * 8 + tq * 2;
            float b0 = 0.f, b1 = 0.f;
            if (bias) { b0 = bias[col]; b1 = bias[col + 1]; }
            *(float2*)(C + (size_t)row * N + col) =
                make_float2(c[mt][nt][0] + b0, c[mt][nt][1] + b1);
            *(float2*)(C + (size_t)(row + 8) * N + col) =
                make_float2(c[mt][nt][2] + b0, c[mt][nt][3] + b1);
        }
    }
}

// ---------------- block reduction helpers (blockDim == 256) ----------------
__device__ __forceinline__ float blk_sum256(float v, float* red8) {
    int tid = threadIdx.x, lane = tid & 31, w = tid >> 5;
    #pragma unroll
    for (int o = 16; o; o >>= 1) v += __shfl_xor_sync(0xffffffffu, v, o);
    __syncthreads();
    if (lane == 0) red8[w] = v;
    __syncthreads();
    if (tid == 0) { float t = 0.f; for (int k = 0; k < 8; k++) t += red8[k]; red8[0] = t; }
    __syncthreads();
    return red8[0];
}

__device__ __forceinline__ float blk_max256(float v, float* red8) {
    int tid = threadIdx.x, lane = tid & 31, w = tid >> 5;
    #pragma unroll
    for (int o = 16; o; o >>= 1) v = fmaxf(v, __shfl_xor_sync(0xffffffffu, v, o));
    __syncthreads();
    if (lane == 0) red8[w] = v;
    __syncthreads();
    if (tid == 0) { float t = red8[0]; for (int k = 1; k < 8; k++) t = fmaxf(t, red8[k]); red8[0] = t; }
    __syncthreads();
    return red8[0];
}

// ---------------- misc kernels ----------------
__global__ void copy_f4(const float4* __restrict__ src, float4* __restrict__ dst, int n4) {
    int i = blockIdx.x * blockDim.x + threadIdx.x;
    if (i < n4) dst[i] = src[i];
}

// dst[f][c] = gatW[h][f][o], c = h*128+o   ->  [K=ED][N=GH] layout for gemm
__global__ void reorder_gatw(const float* __restrict__ src, float* __restrict__ dst) {
    int idx = blockIdx.x * 256 + threadIdx.x;   // grid covers exactly 1M
    int f = idx >> 10, c = idx & 1023, h = c >> 7, o = c & 127;
    dst[idx] = src[((size_t)h * 1024 + f) * 128 + o];
}

// ---------------- CSR build (adj > 0) ----------------
__global__ void csr_count(const float* __restrict__ adj, int* __restrict__ deg) {
    int w = (blockIdx.x * blockDim.x + threadIdx.x) >> 5;
    int lane = threadIdx.x & 31;
    if (w >= NN_) return;
    const float* row = adj + (size_t)w * NN_;
    int cnt = 0;
    for (int c = 0; c < NN_/32; c++) {
        unsigned m = __ballot_sync(0xffffffffu, row[c*32 + lane] > 0.f);
        cnt += __popc(m);
    }
    if (lane == 0) deg[w] = cnt;
}

__global__ void csr_scan(const int* __restrict__ deg, int* __restrict__ rowptr) {
    __shared__ int ps[128];
    int t = threadIdx.x; // 128
    int s = 0;
    for (int i = 0; i < 16; i++) s += deg[t*16 + i];
    ps[t] = s;
    __syncthreads();
    if (t == 0) { int run = 0; for (int i = 0; i < 128; i++) { int v = ps[i]; ps[i] = run; run += v; } }
    __syncthreads();
    int run = ps[t];
    for (int i = 0; i < 16; i++) { rowptr[t*16 + i] = run; run += deg[t*16 + i]; }
    if (t == 127) rowptr[NN_] = run;
}

__global__ void csr_fill(const float* __restrict__ adj, const int* __restrict__ rowptr,
                         int* __restrict__ colidx) {
    int w = (blockIdx.x * blockDim.x + threadIdx.x) >> 5;
    int lane = threadIdx.x & 31;
    if (w >= NN_) return;
    const float* row = adj + (size_t)w * NN_;
    int base = rowptr[w];
    for (int c = 0; c < NN_/32; c++) {
        int j = c*32 + lane;
        bool p = row[j] > 0.f;
        unsigned m = __ballot_sync(0xffffffffu, p);
        if (p) colidx[base + __popc(m & ((1u << lane) - 1u))] = j;
        base += __popc(m);
    }
}

// ---------------- GAT pieces ----------------
__global__ void gat_scores(const float* __restrict__ Wh, const float* __restrict__ a1,
                           const float* __restrict__ a2, float* __restrict__ s1,
                           float* __restrict__ s2) {
    int n = blockIdx.x;
    int w = threadIdx.x >> 5, lane = threadIdx.x & 31;  // 8 warps = 8 heads
    const float* wr  = Wh + (size_t)n * GH + w * HD;
    const float* a1p = a1 + w * HD;
    const float* a2p = a2 + w * HD;
    float v1 = 0.f, v2 = 0.f;
    for (int o = lane; o < HD; o += 32) { float x = wr[o]; v1 += x * a1p[o]; v2 += x * a2p[o]; }
    #pragma unroll
    for (int o = 16; o; o >>= 1) {
        v1 += __shfl_xor_sync(0xffffffffu, v1, o);
        v2 += __shfl_xor_sync(0xffffffffu, v2, o);
    }
    if (lane == 0) { s1[n*NH + w] = v1; s2[n*NH + w] = v2; }
}

__global__ void __launch_bounds__(256) gat_aggregate(
    const float* __restrict__ Wh, const float* __restrict__ s1,
    const float* __restrict__ s2, const int* __restrict__ rowptr,
    const int* __restrict__ colidx, float* __restrict__ out)
{
    const int i = blockIdx.x, tid = threadIdx.x, lane = tid & 31, w = tid >> 5;
    __shared__ float s1sh[8], mh[8], zh[8];
    __shared__ float wred[8][8];
    __shared__ float att[128*8];
    __shared__ int   jsh[128];

    if (tid < 8) s1sh[tid] = s1[i*NH + tid];
    const int base = rowptr[i];
    const int deg  = rowptr[i+1] - base;
    __syncthreads();

    float lm[8];
    #pragma unroll
    for (int h = 0; h < 8; h++) lm[h] = -1e30f;
    for (int jj = tid; jj < deg; jj += 256) {
        int j = colidx[base + jj];
        #pragma unroll
        for (int h = 0; h < 8; h++) {
            float e = s1sh[h] + s2[j*NH + h];
            e = e > 0.f ? e : 0.2f * e;
            lm[h] = fmaxf(lm[h], e);
        }
    }
    #pragma unroll
    for (int h = 0; h < 8; h++) {
        #pragma unroll
        for (int o = 16; o; o >>= 1) lm[h] = fmaxf(lm[h], __shfl_xor_sync(0xffffffffu, lm[h], o));
    }
    if (lane == 0) {
        for (int h = 0; h < 8; h++) wred[w][h] = lm[h];
    }
    __syncthreads();
    if (tid < 8) {
        float m = wred[0][tid];
        for (int ww = 1; ww < 8; ww++) m = fmaxf(m, wred[ww][tid]);
        mh[tid] = m;
    }
    __syncthreads();

    float ls[8];
    #pragma unroll
    for (int h = 0; h < 8; h++) ls[h] = 0.f;
    for (int jj = tid; jj < deg; jj += 256) {
        int j = colidx[base + jj];
        #pragma unroll
        for (int h = 0; h < 8; h++) {
            float e = s1sh[h] + s2[j*NH + h];
            e = e > 0.f ? e : 0.2f * e;
            ls[h] += expf(e - mh[h]);
        }
    }
    #pragma unroll
    for (int h = 0; h < 8; h++) {
        #pragma unroll
        for (int o = 16; o; o >>= 1) ls[h] += __shfl_xor_sync(0xffffffffu, ls[h], o);
    }
    __syncthreads();
    if (lane == 0) {
        for (int h = 0; h < 8; h++) wred[w][h] = ls[h];
    }
    __syncthreads();
    if (tid < 8) {
        float s = 0.f;
        for (int ww = 0; ww < 8; ww++) s += wred[ww][tid];
        zh[tid] = s;
    }
    __syncthreads();

    float acc0 = 0.f, acc1 = 0.f, acc2 = 0.f, acc3 = 0.f;
    const int c0 = tid, c1 = tid + 256, c2 = tid + 512, c3 = tid + 768;
    const int h0 = c0 >> 7, h1 = c1 >> 7, h2 = c2 >> 7, h3 = c3 >> 7;
    for (int cs = 0; cs < deg; cs += 128) {
        const int nck = min(128, deg - cs);
        __syncthreads();
        for (int idx = tid; idx < nck; idx += 256) jsh[idx] = colidx[base + cs + idx];
        for (int idx = tid; idx < nck * 8; idx += 256) {
            int jj = idx >> 3, h = idx & 7;
            int j = colidx[base + cs + jj];
            float e = s1sh[h] + s2[j*NH + h];
            e = e > 0.f ? e : 0.2f * e;
            att[idx] = expf(e - mh[h]) / zh[h];
        }
        __syncthreads();
        for (int jj = 0; jj < nck; jj++) {
            const float* wr = Wh + (size_t)jsh[jj] * GH;
            const float* at = att + jj * 8;
            acc0 += at[h0] * wr[c0];
            acc1 += at[h1] * wr[c1];
            acc2 += at[h2] * wr[c2];
            acc3 += at[h3] * wr[c3];
        }
    }
    float* orow = out + (size_t)i * GH;
    orow[c0] = acc0; orow[c1] = acc1; orow[c2] = acc2; orow[c3] = acc3;
}

// ---------------- LN + activation ----------------
__global__ void ln_act(const float* __restrict__ X, const float* __restrict__ g,
                       const float* __restrict__ b, float* __restrict__ out, int mode) {
    __shared__ float red8[8];
    int row = blockIdx.x, tid = threadIdx.x;
    const float* xr = X + (size_t)row * 1024;
    float v[4];
    #pragma unroll
    for (int k = 0; k < 4; k++) v[k] = xr[tid + 256*k];
    float s = v[0] + v[1] + v[2] + v[3];
    s = blk_sum256(s, red8);
    float mu = s * (1.f/1024.f);
    float q = 0.f;
    #pragma unroll
    for (int k = 0; k < 4; k++) { float d = v[k] - mu; q += d * d; }
    q = blk_sum256(q, red8);
    float rstd = rsqrtf(q * (1.f/1024.f) + 1e-5f);
    float* orow = out + (size_t)row * 1024;
    #pragma unroll
    for (int k = 0; k < 4; k++) {
        int c = tid + 256*k;
        float y = (v[k] - mu) * rstd * g[c] + b[c];
        if (mode == 0) {
            orow[c] = y * 0.5f * (1.f + erff(y * 0.70710678118654752f));
        } else {
            float e = y > 0.f ? y : expm1f(y);
            orow[c] += e;
        }
    }
}

__global__ void l2norm_rows(const float* __restrict__ X, float* __restrict__ out) {
    __shared__ float red8[8];
    int row = blockIdx.x, tid = threadIdx.x;
    const float* xr = X + (size_t)row * 1024;
    float v[4];
    #pragma unroll
    for (int k = 0; k < 4; k++) v[k] = xr[tid + 256*k];
    float q = v[0]*v[0] + v[1]*v[1] + v[2]*v[2] + v[3]*v[3];
    q = blk_sum256(q, red8);
    float inv = 1.f / fmaxf(sqrtf(q), 1e-12f);
    float* orow = out + (size_t)row * 1024;
    #pragma unroll
    for (int k = 0; k < 4; k++) orow[tid + 256*k] = v[k] * inv;
}

__global__ void rowdot(const float* __restrict__ A, const float* __restrict__ B,
                       float* __restrict__ out) {
    __shared__ float red8[8];
    int row = blockIdx.x, tid = threadIdx.x;
    const float* ar = A + (size_t)row * 1024;
    const float* br = B + (size_t)row * 1024;
    float s = 0.f;
    #pragma unroll
    for (int k = 0; k < 4; k++) { int c = tid + 256*k; s += ar[c] * br[c]; }
    s = blk_sum256(s, red8);
    if (tid == 0) out[row] = s;
}

__global__ void lse_rows(const float* __restrict__ neg, float* __restrict__ infoRow) {
    __shared__ float red8[8];
    int row = blockIdx.x, tid = threadIdx.x;
    const float* r = neg + (size_t)row * 1024;
    float v[4];
    #pragma unroll
    for (int k = 0; k < 4; k++) v[k] = r[tid + 256*k] * 20.0f;  // 1/TEMP
    float m = fmaxf(fmaxf(v[0], v[1]), fmaxf(v[2], v[3]));
    m = blk_max256(m, red8);
    float s = 0.f;
    #pragma unroll
    for (int k = 0; k < 4; k++) s += expf(v[k] - m);
    s = blk_sum256(s, red8);
    if (tid == 0) {
        float pos = r[row] * 20.0f;
        float lse = m + logf(expf(pos - m) + s);
        infoRow[row] = lse - pos;
    }
}

__global__ void finalize_k(const float* __restrict__ infoRow, const float* __restrict__ lapRow,
                           float* __restrict__ out, int out_size) {
    __shared__ float ri[32], rl[32];
    int tid = threadIdx.x, lane = tid & 31, w = tid >> 5; // 1024 threads
    float vi = infoRow[tid];
    float vl = lapRow[tid] + lapRow[tid + 1024];
    #pragma unroll
    for (int o = 16; o; o >>= 1) {
        vi += __shfl_xor_sync(0xffffffffu, vi, o);
        vl += __shfl_xor_sync(0xffffffffu, vl, o);
    }
    if (lane == 0) { ri[w] = vi; rl[w] = vl; }
    __syncthreads();
    if (tid == 0) {
        float si = 0.f, sl = 0.f;
        for (int k = 0; k < 32; k++) { si += ri[k]; sl += rl[k]; }
        float info = si / 1024.f;
        float lap  = sl / 2048.f;
        float total = info + 0.1f * lap;
        out[0] = total;
        if (out_size > 1) out[1] = info;
        if (out_size > 2) out[2] = lap;
    }
}

// ---------------- host ----------------
extern "C" void kernel_launch(void* const* d_in, const int* in_sizes, int n_in,
                              void* d_out, int out_size) {
    const float* query = (const float*)d_in[0];
    const float* docs  = (const float*)d_in[1];
    const float* nodes = (const float*)d_in[2];
    const float* adj   = (const float*)d_in[3];
    const float* lapl  = (const float*)d_in[4];
    const float* qW1 = (const float*)d_in[5];  const float* qb1 = (const float*)d_in[6];
    const float* qg  = (const float*)d_in[7];  const float* qbt = (const float*)d_in[8];
    const float* qW2 = (const float*)d_in[9];  const float* qb2 = (const float*)d_in[10];
    const float* dW1 = (const float*)d_in[11]; const float* db1 = (const float*)d_in[12];
    const float* dg  = (const float*)d_in[13]; const float* dbt = (const float*)d_in[14];
    const float* dW2 = (const float*)d_in[15]; const float* db2 = (const float*)d_in[16];
    const float* gatW = (const float*)d_in[17];
    const float* a1   = (const float*)d_in[18];
    const float* a2   = (const float*)d_in[19];
    const float* ln_g = (const float*)d_in[20];
    const float* ln_b = (const float*)d_in[21];
    const float* poW  = (const float*)d_in[22];
    const float* pob  = (const float*)d_in[23];

    void* tp;
    float *px, *pWl, *pWh, *ps1, *ps2, *ph, *pG, *pLG, *pt1, *pt2, *pq, *pp, *pneg, *pinfo, *plap;
    int *pdeg, *prowptr, *pcolidx;
    cudaGetSymbolAddress(&tp, g_x);   px  = (float*)tp;
    cudaGetSymbolAddress(&tp, g_Wl);  pWl = (float*)tp;
    cudaGetSymbolAddress(&tp, g_Wh);  pWh = (float*)tp;
    cudaGetSymbolAddress(&tp, g_s1);  ps1 = (float*)tp;
    cudaGetSymbolAddress(&tp, g_s2);  ps2 = (float*)tp;
    cudaGetSymbolAddress(&tp, g_h);   ph  = (float*)tp;
    cudaGetSymbolAddress(&tp, g_G);   pG  = (float*)tp;
    cudaGetSymbolAddress(&tp, g_LG);  pLG = (float*)tp;
    cudaGetSymbolAddress(&tp, g_t1);  pt1 = (float*)tp;
    cudaGetSymbolAddress(&tp, g_t2);  pt2 = (float*)tp;
    cudaGetSymbolAddress(&tp, g_q);   pq  = (float*)tp;
    cudaGetSymbolAddress(&tp, g_p);   pp  = (float*)tp;
    cudaGetSymbolAddress(&tp, g_neg); pneg = (float*)tp;
    cudaGetSymbolAddress(&tp, g_infoRow); pinfo = (float*)tp;
    cudaGetSymbolAddress(&tp, g_lapRow);  plap  = (float*)tp;
    cudaGetSymbolAddress(&tp, g_deg);     pdeg    = (int*)tp;
    cudaGetSymbolAddress(&tp, g_rowptr);  prowptr = (int*)tp;
    cudaGetSymbolAddress(&tp, g_colidx);  pcolidx = (int*)tp;

    cudaFuncSetAttribute(gemm_tf32<0>, cudaFuncAttributeMaxDynamicSharedMemorySize, GSMEM_BYTES);
    cudaFuncSetAttribute(gemm_tf32<1>, cudaFuncAttributeMaxDynamicSharedMemorySize, GSMEM_BYTES);

    // x = node_embeds
    copy_f4<<<(NN_*ED/4 + 255)/256, 256>>>((const float4*)nodes, (float4*)px, NN_*ED/4);

    // CSR of adj
    csr_count<<<NN_*32/256, 256>>>(adj, pdeg);
    csr_scan<<<1, 128>>>(pdeg, prowptr);
    csr_fill<<<NN_*32/256, 256>>>(adj, prowptr, pcolidx);

    // GNN layers
    for (int l = 0; l < NL; l++) {
        reorder_gatw<<<(ED*GH)/256, 256>>>(gatW + (size_t)l*NH*ED*HD, pWl);
        gemm_tf32<0><<<dim3(GH/128, NN_/128), 256, GSMEM_BYTES>>>(px, pWl, nullptr, pWh, NN_, GH, ED);
        gat_scores<<<NN_, 256>>>(pWh, a1 + l*NH*HD, a2 + l*NH*HD, ps1, ps2);
        gat_aggregate<<<NN_, 256>>>(pWh, ps1, ps2, prowptr, pcolidx, ph);
        ln_act<<<NN_, 256>>>(ph, ln_g + l*GH, ln_b + l*GH, px, 1);
    }

    // graph_embeds + laplacian term  (poW is [GH][ED] = [K][N]; G is [NN_][ED] = [K][N])
    gemm_tf32<0><<<dim3(ED/128, NN_/128), 256, GSMEM_BYTES>>>(px, poW, pob, pG, NN_, ED, GH);
    gemm_tf32<0><<<dim3(ED/128, NN_/128), 256, GSMEM_BYTES>>>(lapl, pG, nullptr, pLG, NN_, ED, NN_);
    rowdot<<<NN_, 256>>>(pG, pLG, plap);

    // query MLP -> q
    gemm_tf32<0><<<dim3(ED/128, BB/128), 256, GSMEM_BYTES>>>(query, qW1, qb1, pt1, BB, ED, ED);
    ln_act<<<BB, 256>>>(pt1, qg, qbt, pt2, 0);
    gemm_tf32<0><<<dim3(ED/128, BB/128), 256, GSMEM_BYTES>>>(pt2, qW2, qb2, pt1, BB, ED, ED);
    l2norm_rows<<<BB, 256>>>(pt1, pq);

    // doc MLP -> p
    gemm_tf32<0><<<dim3(ED/128, BB/128), 256, GSMEM_BYTES>>>(docs, dW1, db1, pt1, BB, ED, ED);
    ln_act<<<BB, 256>>>(pt1, dg, dbt, pt2, 0);
    gemm_tf32<0><<<dim3(ED/128, BB/128), 256, GSMEM_BYTES>>>(pt2, dW2, db2, pt1, BB, ED, ED);
    l2norm_rows<<<BB, 256>>>(pt1, pp);

    // neg similarity + losses (B = p stored [N,K] -> TRANSB=1)
    gemm_tf32<1><<<dim3(BB/128, BB/128), 256, GSMEM_BYTES>>>(pq, pp, nullptr, pneg, BB, BB, ED);
    lse_rows<<<BB, 256>>>(pneg, pinfo);
    finalize_k<<<1, 1024>>>(pinfo, plap, (float*)d_out, out_size);
}

// round 6
// speedup vs baseline: 3.3033x; 1.8188x over previous
#include <cuda_runtime.h>
#include <cuda_bf16.h>
#include <math.h>

// Problem dims (fixed per reference)
#define ED   1024
#define GH   1024
#define NL   3
#define NH   8
#define HD   128
#define NN_  2048   // graph nodes
#define BB   1024   // batch

// ---------------- scratch (static device globals; no allocation) ----------------
__device__ float g_x [NN_*GH];
__device__ float g_Wl[ED*GH];
__device__ float g_Wh[NN_*GH];
__device__ float g_s1[NN_*NH];
__device__ float g_s2[NN_*NH];
__device__ float g_h [NN_*GH];
__device__ float g_G [NN_*ED];
__device__ float g_LG[NN_*ED];
__device__ float g_t1[BB*ED];
__device__ float g_t2[BB*ED];
__device__ float g_t3[BB*ED];
__device__ float g_t4[BB*ED];
__device__ float g_q [BB*ED];
__device__ float g_p [BB*ED];
__device__ float g_neg[BB*BB];
__device__ float g_infoRow[BB];
__device__ float g_lapRow[NN_];
__device__ int   g_deg[NN_];
__device__ int   g_rowptr[NN_+1];
__device__ int   g_colidx[NN_*NN_];

__device__ __forceinline__ unsigned f2tf32(float x) {
    unsigned r; asm("cvt.rna.tf32.f32 %0, %1;" : "=r"(r) : "f"(x)); return r;
}
__device__ __forceinline__ unsigned smem_u32(const void* p) {
    unsigned a;
    asm("{ .reg .u64 t; cvta.to.shared.u64 t, %1; cvt.u32.u64 %0, t; }" : "=r"(a) : "l"(p));
    return a;
}
__device__ __forceinline__ void cpasync16(unsigned dst, const void* src) {
    asm volatile("cp.async.cg.shared.global [%0], [%1], 16;" :: "r"(dst), "l"(src));
}

// ================= cp.async 3-stage pipelined TF32 GEMM (B in [K,N]) =================
// C[M,N] = A[M,K] @ B[K,N] + bias. 128x128x32 tile, 256 threads.
// A smem: [m][36] (pad 32->36, conflict-free frag reads). B smem: [k][132].
// Fragments are rounded to tf32 with cvt.rna at smem->reg load time (precision!).
#define AST (128*36)
#define BST (32*132)
#define GC_SMEM ((3*(AST+BST))*4)

__global__ void __launch_bounds__(256, 1) gemm_ca(
    const float* __restrict__ A, const float* __restrict__ B,
    const float* __restrict__ bias, float* __restrict__ C,
    int M, int N, int K)
{
    extern __shared__ float sm[];
    const float* As = sm;
    const float* Bs = sm + 3*AST;
    const unsigned smem_base = smem_u32(sm);

    const int tid = threadIdx.x;
    const int w   = tid >> 5, lane = tid & 31;
    const int g   = lane >> 2, tq = lane & 3;
    const int wm  = w & 3, wn = w >> 2;
    const int bm  = blockIdx.y * 128, bn = blockIdx.x * 128;
    const int nck = K >> 5;

    float c[2][8][4];
    #pragma unroll
    for (int mt = 0; mt < 2; mt++)
        #pragma unroll
        for (int nt = 0; nt < 8; nt++)
            #pragma unroll
            for (int j = 0; j < 4; j++) c[mt][nt][j] = 0.f;

    auto stage_load = [&](int ck, int st) {
        const unsigned abase = smem_base + (unsigned)(st * AST) * 4u;
        const unsigned bbase = smem_base + (unsigned)(3*AST + st * BST) * 4u;
        #pragma unroll
        for (int i = 0; i < 4; i++) {
            int idx = tid + 256 * i;
            int m = idx >> 3, c4 = idx & 7;
            cpasync16(abase + (unsigned)(m * 36 + c4 * 4) * 4u,
                      A + (size_t)(bm + m) * K + ck * 32 + c4 * 4);
        }
        #pragma unroll
        for (int i = 0; i < 4; i++) {
            int idx = tid + 256 * i;
            int kr = idx >> 5, c4 = idx & 31;
            cpasync16(bbase + (unsigned)(kr * 132 + c4 * 4) * 4u,
                      B + (size_t)(ck * 32 + kr) * N + bn + c4 * 4);
        }
    };

    stage_load(0, 0);
    asm volatile("cp.async.commit_group;" ::: "memory");
    stage_load(1, 1);
    asm volatile("cp.async.commit_group;" ::: "memory");

    for (int ck = 0; ck < nck; ck++) {
        asm volatile("cp.async.wait_group 1;" ::: "memory");
        __syncthreads();
        if (ck + 2 < nck) stage_load(ck + 2, (ck + 2) % 3);
        asm volatile("cp.async.commit_group;" ::: "memory");

        const int st = ck % 3;
        const float* Ast = As + st * AST;
        const float* Bst = Bs + st * BST;
        #pragma unroll
        for (int ks = 0; ks < 4; ks++) {
            unsigned a[2][4], b[8][2];
            #pragma unroll
            for (int mt = 0; mt < 2; mt++) {
                const int r0 = wm * 32 + g + mt * 16;
                a[mt][0] = f2tf32(Ast[r0 * 36 + ks * 8 + tq]);
                a[mt][1] = f2tf32(Ast[(r0 + 8) * 36 + ks * 8 + tq]);
                a[mt][2] = f2tf32(Ast[r0 * 36 + ks * 8 + tq + 4]);
                a[mt][3] = f2tf32(Ast[(r0 + 8) * 36 + ks * 8 + tq + 4]);
            }
            const int bn0 = wn * 64 + g;
            #pragma unroll
            for (int nt = 0; nt < 8; nt++) {
                b[nt][0] = f2tf32(Bst[(ks * 8 + tq) * 132 + bn0 + nt * 8]);
                b[nt][1] = f2tf32(Bst[(ks * 8 + tq + 4) * 132 + bn0 + nt * 8]);
            }
            #pragma unroll
            for (int mt = 0; mt < 2; mt++)
                #pragma unroll
                for (int nt = 0; nt < 8; nt++)
                    asm volatile(
                        "mma.sync.aligned.m16n8k8.row.col.f32.tf32.tf32.f32 "
                        "{%0,%1,%2,%3}, {%4,%5,%6,%7}, {%8,%9}, {%0,%1,%2,%3};"
                        : "+f"(c[mt][nt][0]), "+f"(c[mt][nt][1]),
                          "+f"(c[mt][nt][2]), "+f"(c[mt][nt][3])
                        : "r"(a[mt][0]), "r"(a[mt][1]), "r"(a[mt][2]), "r"(a[mt][3]),
                          "r"(b[nt][0]), "r"(b[nt][1]));
        }
        __syncthreads();
    }

    #pragma unroll
    for (int mt = 0; mt < 2; mt++) {
        int row = bm + wm * 32 + mt * 16 + g;
        #pragma unroll
        for (int nt = 0; nt < 8; nt++) {
            int col = bn + wn * 64 + nt * 8 + tq * 2;
            float b0 = 0.f, b1 = 0.f;
            if (bias) { b0 = bias[col]; b1 = bias[col + 1]; }
            *(float2*)(C + (size_t)row * N + col) =
                make_float2(c[mt][nt][0] + b0, c[mt][nt][1] + b1);
            *(float2*)(C + (size_t)(row + 8) * N + col) =
                make_float2(c[mt][nt][2] + b0, c[mt][nt][3] + b1);
        }
    }
}

// ================= register-staged TF32 GEMM, B in [N,K] (for q@p^T) =================
#define GSMEM_BYTES (2 * 32 * 132 * 4 * 2)

__global__ void __launch_bounds__(256, 1) gemm_nt_tf32(
    const float* __restrict__ A, const float* __restrict__ B,
    float* __restrict__ C, int M, int N, int K)
{
    extern __shared__ unsigned smem_u[];
    unsigned (*As)[32][132] = reinterpret_cast<unsigned(*)[32][132]>(smem_u);
    unsigned (*Bs)[32][132] = reinterpret_cast<unsigned(*)[32][132]>(smem_u + 2*32*132);

    const int tid = threadIdx.x;
    const int w   = tid >> 5, lane = tid & 31;
    const int g   = lane >> 2, tq = lane & 3;
    const int wm  = w & 3, wn = w >> 2;
    const int bm  = blockIdx.y * 128, bn = blockIdx.x * 128;
    const int nck = K >> 5;

    float4 av[4], bv[4];
    float c[2][8][4];
    #pragma unroll
    for (int mt = 0; mt < 2; mt++)
        #pragma unroll
        for (int nt = 0; nt < 8; nt++)
            #pragma unroll
            for (int j = 0; j < 4; j++) c[mt][nt][j] = 0.f;

    for (int ck = 0; ck <= nck; ck++) {
        if (ck < nck) {
            #pragma unroll
            for (int i = 0; i < 4; i++) {
                int wt = w * 4 + i;
                int c4 = wt & 7;
                int r  = ((wt & 24) << 2) + lane;
                av[i] = *(const float4*)(A + (size_t)(bm + r) * K + ck * 32 + c4 * 4);
                bv[i] = *(const float4*)(B + (size_t)(bn + r) * K + ck * 32 + c4 * 4);
            }
        }
        if (ck > 0) {
            const int cb = (ck - 1) & 1;
            #pragma unroll
            for (int s = 0; s < 4; s++) {
                unsigned a[2][4], b[8][2];
                const unsigned* A0 = As[cb][s * 8 + tq];
                const unsigned* A4 = As[cb][s * 8 + tq + 4];
                const int am = wm * 32 + g;
                #pragma unroll
                for (int mt = 0; mt < 2; mt++) {
                    a[mt][0] = A0[am + mt * 16];
                    a[mt][1] = A0[am + mt * 16 + 8];
                    a[mt][2] = A4[am + mt * 16];
                    a[mt][3] = A4[am + mt * 16 + 8];
                }
                const unsigned* B0 = Bs[cb][s * 8 + tq];
                const unsigned* B4 = Bs[cb][s * 8 + tq + 4];
                const int bn0 = wn * 64 + g;
                #pragma unroll
                for (int nt = 0; nt < 8; nt++) {
                    b[nt][0] = B0[bn0 + nt * 8];
                    b[nt][1] = B4[bn0 + nt * 8];
                }
                #pragma unroll
                for (int mt = 0; mt < 2; mt++)
                    #pragma unroll
                    for (int nt = 0; nt < 8; nt++)
                        asm volatile(
                            "mma.sync.aligned.m16n8k8.row.col.f32.tf32.tf32.f32 "
                            "{%0,%1,%2,%3}, {%4,%5,%6,%7}, {%8,%9}, {%0,%1,%2,%3};"
                            : "+f"(c[mt][nt][0]), "+f"(c[mt][nt][1]),
                              "+f"(c[mt][nt][2]), "+f"(c[mt][nt][3])
                            : "r"(a[mt][0]), "r"(a[mt][1]), "r"(a[mt][2]), "r"(a[mt][3]),
                              "r"(b[nt][0]), "r"(b[nt][1]));
            }
        }
        if (ck < nck) {
            const int sb = ck & 1;
            #pragma unroll
            for (int i = 0; i < 4; i++) {
                int wt = w * 4 + i;
                int c4 = wt & 7;
                int r  = ((wt & 24) << 2) + lane;
                As[sb][c4 * 4 + 0][r] = f2tf32(av[i].x);
                As[sb][c4 * 4 + 1][r] = f2tf32(av[i].y);
                As[sb][c4 * 4 + 2][r] = f2tf32(av[i].z);
                As[sb][c4 * 4 + 3][r] = f2tf32(av[i].w);
                Bs[sb][c4 * 4 + 0][r] = f2tf32(bv[i].x);
                Bs[sb][c4 * 4 + 1][r] = f2tf32(bv[i].y);
                Bs[sb][c4 * 4 + 2][r] = f2tf32(bv[i].z);
                Bs[sb][c4 * 4 + 3][r] = f2tf32(bv[i].w);
            }
        }
        __syncthreads();
    }

    #pragma unroll
    for (int mt = 0; mt < 2; mt++) {
        int row = bm + wm * 32 + mt * 16 + g;
        #pragma unroll
        for (int nt = 0; nt < 8; nt++) {
            int col = bn + wn * 64 + nt * 8 + tq * 2;
            *(float2*)(C + (size_t)row * N + col) =
                make_float2(c[mt][nt][0], c[mt][nt][1]);
            *(float2*)(C + (size_t)(row + 8) * N + col) =
                make_float2(c[mt][nt][2], c[mt][nt][3]);
        }
    }
}

// ---------------- block reduction helpers (blockDim == 256) ----------------
__device__ __forceinline__ float blk_sum256(float v, float* red8) {
    int tid = threadIdx.x, lane = tid & 31, w = tid >> 5;
    #pragma unroll
    for (int o = 16; o; o >>= 1) v += __shfl_xor_sync(0xffffffffu, v, o);
    __syncthreads();
    if (lane == 0) red8[w] = v;
    __syncthreads();
    if (tid == 0) { float t = 0.f; for (int k = 0; k < 8; k++) t += red8[k]; red8[0] = t; }
    __syncthreads();
    return red8[0];
}

__device__ __forceinline__ float blk_max256(float v, float* red8) {
    int tid = threadIdx.x, lane = tid & 31, w = tid >> 5;
    #pragma unroll
    for (int o = 16; o; o >>= 1) v = fmaxf(v, __shfl_xor_sync(0xffffffffu, v, o));
    __syncthreads();
    if (lane == 0) red8[w] = v;
    __syncthreads();
    if (tid == 0) { float t = red8[0]; for (int k = 1; k < 8; k++) t = fmaxf(t, red8[k]); red8[0] = t; }
    __syncthreads();
    return red8[0];
}

// ---------------- misc kernels ----------------
__global__ void copy_f4(const float4* __restrict__ src, float4* __restrict__ dst, int n4) {
    int i = blockIdx.x * blockDim.x + threadIdx.x;
    if (i < n4) dst[i] = src[i];
}

// dst[f][c] = gatW[h][f][o], c = h*128+o   ->  [K=ED][N=GH] layout for gemm
__global__ void reorder_gatw(const float* __restrict__ src, float* __restrict__ dst) {
    int idx = blockIdx.x * 256 + threadIdx.x;   // grid covers exactly 1M
    int f = idx >> 10, c = idx & 1023, h = c >> 7, o = c & 127;
    dst[idx] = src[((size_t)h * 1024 + f) * 128 + o];
}

// ---------------- CSR build (adj > 0) ----------------
__global__ void csr_count(const float* __restrict__ adj, int* __restrict__ deg) {
    int w = (blockIdx.x * blockDim.x + threadIdx.x) >> 5;
    int lane = threadIdx.x & 31;
    if (w >= NN_) return;
    const float* row = adj + (size_t)w * NN_;
    int cnt = 0;
    for (int c = 0; c < NN_/32; c++) {
        unsigned m = __ballot_sync(0xffffffffu, row[c*32 + lane] > 0.f);
        cnt += __popc(m);
    }
    if (lane == 0) deg[w] = cnt;
}

__global__ void csr_scan(const int* __restrict__ deg, int* __restrict__ rowptr) {
    __shared__ int ps[128];
    int t = threadIdx.x; // 128
    int s = 0;
    for (int i = 0; i < 16; i++) s += deg[t*16 + i];
    ps[t] = s;
    __syncthreads();
    if (t == 0) { int run = 0; for (int i = 0; i < 128; i++) { int v = ps[i]; ps[i] = run; run += v; } }
    __syncthreads();
    int run = ps[t];
    for (int i = 0; i < 16; i++) { rowptr[t*16 + i] = run; run += deg[t*16 + i]; }
    if (t == 127) rowptr[NN_] = run;
}

__global__ void csr_fill(const float* __restrict__ adj, const int* __restrict__ rowptr,
                         int* __restrict__ colidx) {
    int w = (blockIdx.x * blockDim.x + threadIdx.x) >> 5;
    int lane = threadIdx.x & 31;
    if (w >= NN_) return;
    const float* row = adj + (size_t)w * NN_;
    int base = rowptr[w];
    for (int c = 0; c < NN_/32; c++) {
        int j = c*32 + lane;
        bool p = row[j] > 0.f;
        unsigned m = __ballot_sync(0xffffffffu, p);
        if (p) colidx[base + __popc(m & ((1u << lane) - 1u))] = j;
        base += __popc(m);
    }
}

// ---------------- GAT pieces ----------------
__global__ void gat_scores(const float* __restrict__ Wh, const float* __restrict__ a1,
                           const float* __restrict__ a2, float* __restrict__ s1,
                           float* __restrict__ s2) {
    int n = blockIdx.x;
    int w = threadIdx.x >> 5, lane = threadIdx.x & 31;  // 8 warps = 8 heads
    const float* wr  = Wh + (size_t)n * GH + w * HD;
    const float* a1p = a1 + w * HD;
    const float* a2p = a2 + w * HD;
    float v1 = 0.f, v2 = 0.f;
    for (int o = lane; o < HD; o += 32) { float x = wr[o]; v1 += x * a1p[o]; v2 += x * a2p[o]; }
    #pragma unroll
    for (int o = 16; o; o >>= 1) {
        v1 += __shfl_xor_sync(0xffffffffu, v1, o);
        v2 += __shfl_xor_sync(0xffffffffu, v2, o);
    }
    if (lane == 0) { s1[n*NH + w] = v1; s2[n*NH + w] = v2; }
}

__global__ void __launch_bounds__(256) gat_aggregate(
    const float* __restrict__ Wh, const float* __restrict__ s1,
    const float* __restrict__ s2, const int* __restrict__ rowptr,
    const int* __restrict__ colidx, float* __restrict__ out)
{
    const int i = blockIdx.x, tid = threadIdx.x, lane = tid & 31, w = tid >> 5;
    __shared__ float s1sh[8], mh[8], zh[8];
    __shared__ float wred[8][8];
    __shared__ float att[128*8];
    __shared__ int   jsh[128];

    if (tid < 8) s1sh[tid] = s1[i*NH + tid];
    const int base = rowptr[i];
    const int deg  = rowptr[i+1] - base;
    __syncthreads();

    float lm[8];
    #pragma unroll
    for (int h = 0; h < 8; h++) lm[h] = -1e30f;
    for (int jj = tid; jj < deg; jj += 256) {
        int j = colidx[base + jj];
        #pragma unroll
        for (int h = 0; h < 8; h++) {
            float e = s1sh[h] + s2[j*NH + h];
            e = e > 0.f ? e : 0.2f * e;
            lm[h] = fmaxf(lm[h], e);
        }
    }
    #pragma unroll
    for (int h = 0; h < 8; h++) {
        #pragma unroll
        for (int o = 16; o; o >>= 1) lm[h] = fmaxf(lm[h], __shfl_xor_sync(0xffffffffu, lm[h], o));
    }
    if (lane == 0) {
        for (int h = 0; h < 8; h++) wred[w][h] = lm[h];
    }
    __syncthreads();
    if (tid < 8) {
        float m = wred[0][tid];
        for (int ww = 1; ww < 8; ww++) m = fmaxf(m, wred[ww][tid]);
        mh[tid] = m;
    }
    __syncthreads();

    float ls[8];
    #pragma unroll
    for (int h = 0; h < 8; h++) ls[h] = 0.f;
    for (int jj = tid; jj < deg; jj += 256) {
        int j = colidx[base + jj];
        #pragma unroll
        for (int h = 0; h < 8; h++) {
            float e = s1sh[h] + s2[j*NH + h];
            e = e > 0.f ? e : 0.2f * e;
            ls[h] += expf(e - mh[h]);
        }
    }
    #pragma unroll
    for (int h = 0; h < 8; h++) {
        #pragma unroll
        for (int o = 16; o; o >>= 1) ls[h] += __shfl_xor_sync(0xffffffffu, ls[h], o);
    }
    __syncthreads();
    if (lane == 0) {
        for (int h = 0; h < 8; h++) wred[w][h] = ls[h];
    }
    __syncthreads();
    if (tid < 8) {
        float s = 0.f;
        for (int ww = 0; ww < 8; ww++) s += wred[ww][tid];
        zh[tid] = s;
    }
    __syncthreads();

    float acc0 = 0.f, acc1 = 0.f, acc2 = 0.f, acc3 = 0.f;
    const int c0 = tid, c1 = tid + 256, c2 = tid + 512, c3 = tid + 768;
    const int h0 = c0 >> 7, h1 = c1 >> 7, h2 = c2 >> 7, h3 = c3 >> 7;
    for (int cs = 0; cs < deg; cs += 128) {
        const int nck = min(128, deg - cs);
        __syncthreads();
        for (int idx = tid; idx < nck; idx += 256) jsh[idx] = colidx[base + cs + idx];
        for (int idx = tid; idx < nck * 8; idx += 256) {
            int jj = idx >> 3, h = idx & 7;
            int j = colidx[base + cs + jj];
            float e = s1sh[h] + s2[j*NH + h];
            e = e > 0.f ? e : 0.2f * e;
            att[idx] = expf(e - mh[h]) / zh[h];
        }
        __syncthreads();
        int jj = 0;
        for (; jj + 1 < nck; jj += 2) {
            const float* wr0 = Wh + (size_t)jsh[jj] * GH;
            const float* at0 = att + jj * 8;
            const float* wr1 = Wh + (size_t)jsh[jj+1] * GH;
            const float* at1 = att + (jj+1) * 8;
            acc0 += at0[h0] * wr0[c0] + at1[h0] * wr1[c0];
            acc1 += at0[h1] * wr0[c1] + at1[h1] * wr1[c1];
            acc2 += at0[h2] * wr0[c2] + at1[h2] * wr1[c2];
            acc3 += at0[h3] * wr0[c3] + at1[h3] * wr1[c3];
        }
        if (jj < nck) {
            const float* wr = Wh + (size_t)jsh[jj] * GH;
            const float* at = att + jj * 8;
            acc0 += at[h0] * wr[c0];
            acc1 += at[h1] * wr[c1];
            acc2 += at[h2] * wr[c2];
            acc3 += at[h3] * wr[c3];
        }
    }
    float* orow = out + (size_t)i * GH;
    orow[c0] = acc0; orow[c1] = acc1; orow[c2] = acc2; orow[c3] = acc3;
}

// ---------------- LN + activation ----------------
__global__ void ln_act(const float* __restrict__ X, const float* __restrict__ g,
                       const float* __restrict__ b, float* __restrict__ out, int mode) {
    __shared__ float red8[8];
    int row = blockIdx.x, tid = threadIdx.x;
    const float* xr = X + (size_t)row * 1024;
    float v[4];
    #pragma unroll
    for (int k = 0; k < 4; k++) v[k] = xr[tid + 256*k];
    float s = v[0] + v[1] + v[2] + v[3];
    s = blk_sum256(s, red8);
    float mu = s * (1.f/1024.f);
    float q = 0.f;
    #pragma unroll
    for (int k = 0; k < 4; k++) { float d = v[k] - mu; q += d * d; }
    q = blk_sum256(q, red8);
    float rstd = rsqrtf(q * (1.f/1024.f) + 1e-5f);
    float* orow = out + (size_t)row * 1024;
    #pragma unroll
    for (int k = 0; k < 4; k++) {
        int c = tid + 256*k;
        float y = (v[k] - mu) * rstd * g[c] + b[c];
        if (mode == 0) {
            orow[c] = y * 0.5f * (1.f + erff(y * 0.70710678118654752f));
        } else {
            float e = y > 0.f ? y : expm1f(y);
            orow[c] += e;
        }
    }
}

__global__ void l2norm_rows(const float* __restrict__ X, float* __restrict__ out) {
    __shared__ float red8[8];
    int row = blockIdx.x, tid = threadIdx.x;
    const float* xr = X + (size_t)row * 1024;
    float v[4];
    #pragma unroll
    for (int k = 0; k < 4; k++) v[k] = xr[tid + 256*k];
    float q = v[0]*v[0] + v[1]*v[1] + v[2]*v[2] + v[3]*v[3];
    q = blk_sum256(q, red8);
    float inv = 1.f / fmaxf(sqrtf(q), 1e-12f);
    float* orow = out + (size_t)row * 1024;
    #pragma unroll
    for (int k = 0; k < 4; k++) orow[tid + 256*k] = v[k] * inv;
}

__global__ void rowdot(const float* __restrict__ A, const float* __restrict__ B,
                       float* __restrict__ out) {
    __shared__ float red8[8];
    int row = blockIdx.x, tid = threadIdx.x;
    const float* ar = A + (size_t)row * 1024;
    const float* br = B + (size_t)row * 1024;
    float s = 0.f;
    #pragma unroll
    for (int k = 0; k < 4; k++) { int c = tid + 256*k; s += ar[c] * br[c]; }
    s = blk_sum256(s, red8);
    if (tid == 0) out[row] = s;
}

__global__ void lse_rows(const float* __restrict__ neg, float* __restrict__ infoRow) {
    __shared__ float red8[8];
    int row = blockIdx.x, tid = threadIdx.x;
    const float* r = neg + (size_t)row * 1024;
    float v[4];
    #pragma unroll
    for (int k = 0; k < 4; k++) v[k] = r[tid + 256*k] * 20.0f;  // 1/TEMP
    float m = fmaxf(fmaxf(v[0], v[1]), fmaxf(v[2], v[3]));
    m = blk_max256(m, red8);
    float s = 0.f;
    #pragma unroll
    for (int k = 0; k < 4; k++) s += expf(v[k] - m);
    s = blk_sum256(s, red8);
    if (tid == 0) {
        float pos = r[row] * 20.0f;
        float lse = m + logf(expf(pos - m) + s);
        infoRow[row] = lse - pos;
    }
}

__global__ void finalize_k(const float* __restrict__ infoRow, const float* __restrict__ lapRow,
                           float* __restrict__ out, int out_size) {
    __shared__ float ri[32], rl[32];
    int tid = threadIdx.x, lane = tid & 31, w = tid >> 5; // 1024 threads
    float vi = infoRow[tid];
    float vl = lapRow[tid] + lapRow[tid + 1024];
    #pragma unroll
    for (int o = 16; o; o >>= 1) {
        vi += __shfl_xor_sync(0xffffffffu, vi, o);
        vl += __shfl_xor_sync(0xffffffffu, vl, o);
    }
    if (lane == 0) { ri[w] = vi; rl[w] = vl; }
    __syncthreads();
    if (tid == 0) {
        float si = 0.f, sl = 0.f;
        for (int k = 0; k < 32; k++) { si += ri[k]; sl += rl[k]; }
        float info = si / 1024.f;
        float lap  = sl / 2048.f;
        float total = info + 0.1f * lap;
        out[0] = total;
        if (out_size > 1) out[1] = info;
        if (out_size > 2) out[2] = lap;
    }
}

// ---------------- host ----------------
extern "C" void kernel_launch(void* const* d_in, const int* in_sizes, int n_in,
                              void* d_out, int out_size) {
    const float* query = (const float*)d_in[0];
    const float* docs  = (const float*)d_in[1];
    const float* nodes = (const float*)d_in[2];
    const float* adj   = (const float*)d_in[3];
    const float* lapl  = (const float*)d_in[4];
    const float* qW1 = (const float*)d_in[5];  const float* qb1 = (const float*)d_in[6];
    const float* qg  = (const float*)d_in[7];  const float* qbt = (const float*)d_in[8];
    const float* qW2 = (const float*)d_in[9];  const float* qb2 = (const float*)d_in[10];
    const float* dW1 = (const float*)d_in[11]; const float* db1 = (const float*)d_in[12];
    const float* dg  = (const float*)d_in[13]; const float* dbt = (const float*)d_in[14];
    const float* dW2 = (const float*)d_in[15]; const float* db2 = (const float*)d_in[16];
    const float* gatW = (const float*)d_in[17];
    const float* a1   = (const float*)d_in[18];
    const float* a2   = (const float*)d_in[19];
    const float* ln_g = (const float*)d_in[20];
    const float* ln_b = (const float*)d_in[21];
    const float* poW  = (const float*)d_in[22];
    const float* pob  = (const float*)d_in[23];

    void* tp;
    float *px, *pWl, *pWh, *ps1, *ps2, *ph, *pG, *pLG;
    float *pt1, *pt2, *pt3, *pt4, *pq, *pp, *pneg, *pinfo, *plap;
    int *pdeg, *prowptr, *pcolidx;
    cudaGetSymbolAddress(&tp, g_x);   px  = (float*)tp;
    cudaGetSymbolAddress(&tp, g_Wl);  pWl = (float*)tp;
    cudaGetSymbolAddress(&tp, g_Wh);  pWh = (float*)tp;
    cudaGetSymbolAddress(&tp, g_s1);  ps1 = (float*)tp;
    cudaGetSymbolAddress(&tp, g_s2);  ps2 = (float*)tp;
    cudaGetSymbolAddress(&tp, g_h);   ph  = (float*)tp;
    cudaGetSymbolAddress(&tp, g_G);   pG  = (float*)tp;
    cudaGetSymbolAddress(&tp, g_LG);  pLG = (float*)tp;
    cudaGetSymbolAddress(&tp, g_t1);  pt1 = (float*)tp;
    cudaGetSymbolAddress(&tp, g_t2);  pt2 = (float*)tp;
    cudaGetSymbolAddress(&tp, g_t3);  pt3 = (float*)tp;
    cudaGetSymbolAddress(&tp, g_t4);  pt4 = (float*)tp;
    cudaGetSymbolAddress(&tp, g_q);   pq  = (float*)tp;
    cudaGetSymbolAddress(&tp, g_p);   pp  = (float*)tp;
    cudaGetSymbolAddress(&tp, g_neg); pneg = (float*)tp;
    cudaGetSymbolAddress(&tp, g_infoRow); pinfo = (float*)tp;
    cudaGetSymbolAddress(&tp, g_lapRow);  plap  = (float*)tp;
    cudaGetSymbolAddress(&tp, g_deg);     pdeg    = (int*)tp;
    cudaGetSymbolAddress(&tp, g_rowptr);  prowptr = (int*)tp;
    cudaGetSymbolAddress(&tp, g_colidx);  pcolidx = (int*)tp;

    static cudaStream_t sQ = nullptr, sD = nullptr, sC = nullptr;
    static cudaEvent_t evRoot, evQ, evD, evC;
    if (!sQ) {
        cudaStreamCreateWithFlags(&sQ, cudaStreamNonBlocking);
        cudaStreamCreateWithFlags(&sD, cudaStreamNonBlocking);
        cudaStreamCreateWithFlags(&sC, cudaStreamNonBlocking);
        cudaEventCreateWithFlags(&evRoot, cudaEventDisableTiming);
        cudaEventCreateWithFlags(&evQ, cudaEventDisableTiming);
        cudaEventCreateWithFlags(&evD, cudaEventDisableTiming);
        cudaEventCreateWithFlags(&evC, cudaEventDisableTiming);
        cudaFuncSetAttribute(gemm_ca, cudaFuncAttributeMaxDynamicSharedMemorySize, GC_SMEM);
        cudaFuncSetAttribute(gemm_nt_tf32, cudaFuncAttributeMaxDynamicSharedMemorySize, GSMEM_BYTES);
    }

    // fork point
    cudaEventRecord(evRoot, 0);
    cudaStreamWaitEvent(sQ, evRoot, 0);
    cudaStreamWaitEvent(sD, evRoot, 0);
    cudaStreamWaitEvent(sC, evRoot, 0);

    // ---- stream sC: CSR of adj ----
    csr_count<<<NN_*32/256, 256, 0, sC>>>(adj, pdeg);
    csr_scan<<<1, 128, 0, sC>>>(pdeg, prowptr);
    csr_fill<<<NN_*32/256, 256, 0, sC>>>(adj, prowptr, pcolidx);
    cudaEventRecord(evC, sC);

    // ---- stream sD: doc MLP -> p ----
    gemm_ca<<<dim3(ED/128, BB/128), 256, GC_SMEM, sD>>>(docs, dW1, db1, pt3, BB, ED, ED);
    ln_act<<<BB, 256, 0, sD>>>(pt3, dg, dbt, pt4, 0);
    gemm_ca<<<dim3(ED/128, BB/128), 256, GC_SMEM, sD>>>(pt4, dW2, db2, pt3, BB, ED, ED);
    l2norm_rows<<<BB, 256, 0, sD>>>(pt3, pp);
    cudaEventRecord(evD, sD);

    // ---- stream sQ: query MLP -> q, then neg + lse ----
    gemm_ca<<<dim3(ED/128, BB/128), 256, GC_SMEM, sQ>>>(query, qW1, qb1, pt1, BB, ED, ED);
    ln_act<<<BB, 256, 0, sQ>>>(pt1, qg, qbt, pt2, 0);
    gemm_ca<<<dim3(ED/128, BB/128), 256, GC_SMEM, sQ>>>(pt2, qW2, qb2, pt1, BB, ED, ED);
    l2norm_rows<<<BB, 256, 0, sQ>>>(pt1, pq);
    cudaStreamWaitEvent(sQ, evD, 0);
    gemm_nt_tf32<<<dim3(BB/128, BB/128), 256, GSMEM_BYTES, sQ>>>(pq, pp, pneg, BB, BB, ED);
    lse_rows<<<BB, 256, 0, sQ>>>(pneg, pinfo);
    cudaEventRecord(evQ, sQ);

    // ---- default stream: GNN chain ----
    copy_f4<<<(NN_*ED/4 + 255)/256, 256>>>((const float4*)nodes, (float4*)px, NN_*ED/4);
    for (int l = 0; l < NL; l++) {
        reorder_gatw<<<(ED*GH)/256, 256>>>(gatW + (size_t)l*NH*ED*HD, pWl);
        gemm_ca<<<dim3(GH/128, NN_/128), 256, GC_SMEM>>>(px, pWl, nullptr, pWh, NN_, GH, ED);
        gat_scores<<<NN_, 256>>>(pWh, a1 + l*NH*HD, a2 + l*NH*HD, ps1, ps2);
        if (l == 0) cudaStreamWaitEvent(0, evC, 0);
        gat_aggregate<<<NN_, 256>>>(pWh, ps1, ps2, prowptr, pcolidx, ph);
        ln_act<<<NN_, 256>>>(ph, ln_g + l*GH, ln_b + l*GH, px, 1);
    }
    gemm_ca<<<dim3(ED/128, NN_/128), 256, GC_SMEM>>>(px, poW, pob, pG, NN_, ED, GH);
    gemm_ca<<<dim3(ED/128, NN_/128), 256, GC_SMEM>>>(lapl, pG, nullptr, pLG, NN_, ED, NN_);
    rowdot<<<NN_, 256>>>(pG, pLG, plap);

    // ---- join + finalize ----
    cudaStreamWaitEvent(0, evQ, 0);
    finalize_k<<<1, 1024>>>(pinfo, plap, (float*)d_out, out_size);
}

// round 8
// speedup vs baseline: 3.3226x; 1.0058x over previous
#include <cuda_runtime.h>
#include <cuda_bf16.h>
#include <math.h>

// Problem dims (fixed per reference)
#define ED   1024
#define GH   1024
#define NL   3
#define NH   8
#define HD   128
#define NN_  2048   // graph nodes
#define BB   1024   // batch

// ---------------- scratch (static device globals; no allocation) ----------------
__device__ float g_x [NN_*GH];
__device__ float g_Wh[NN_*GH];
__device__ float g_s1[NN_*NH];
__device__ float g_s2[NN_*NH];
__device__ float g_h [NN_*GH];
__device__ float g_G [NN_*ED];
__device__ float g_Gr[NN_*ED];
__device__ float g_LG[NN_*ED];
__device__ float g_t1[BB*ED];
__device__ float g_t2[BB*ED];
__device__ float g_t3[BB*ED];
__device__ float g_t4[BB*ED];
__device__ float g_q [BB*ED];
__device__ float g_p [BB*ED];
__device__ float g_neg[BB*BB];
__device__ float g_infoRow[BB];
__device__ float g_lapRow[NN_];
__device__ float g_Wr[NL*ED*GH];      // rounded+reordered gatW (all layers)
__device__ float g_poWr[GH*ED];       // rounded poW
__device__ float g_laplr[NN_*NN_];    // rounded laplacian
__device__ int   g_deg[NN_];
__device__ int   g_rowptr[NN_+1];
__device__ int   g_colidx[NN_*NN_];

__device__ __forceinline__ unsigned f2tf32(float x) {
    unsigned r; asm("cvt.rna.tf32.f32 %0, %1;" : "=r"(r) : "f"(x)); return r;
}
__device__ __forceinline__ unsigned smem_u32(const void* p) {
    unsigned a;
    asm("{ .reg .u64 t; cvta.to.shared.u64 t, %1; cvt.u32.u64 %0, t; }" : "=r"(a) : "l"(p));
    return a;
}
__device__ __forceinline__ void cpasync16(unsigned dst, const void* src) {
    asm volatile("cp.async.cg.shared.global [%0], [%1], 16;" :: "r"(dst), "l"(src));
}

// ================= cp.async 3-stage pipelined TF32 GEMM (B in [K,N]) =================
// C[M,N] = A[M,K] @ B[K,N] + bias. 128x128x32 tile, 256 threads.
// CVTA/CVTB: round fragment to tf32 at load (false => operand pre-rounded).
// Cr: optional second output = tf32-rounded copy of C (for feeding later GEMMs).
#define AST (128*36)
#define BST (32*132)
#define GC_SMEM ((3*(AST+BST))*4)

template<bool CVTA, bool CVTB>
__global__ void __launch_bounds__(256, 1) gemm_ca(
    const float* __restrict__ A, const float* __restrict__ B,
    const float* __restrict__ bias, float* __restrict__ C,
    float* __restrict__ Cr,
    int M, int N, int K)
{
    extern __shared__ float sm[];
    const float* As = sm;
    const float* Bs = sm + 3*AST;
    const unsigned smem_base = smem_u32(sm);

    const int tid = threadIdx.x;
    const int w   = tid >> 5, lane = tid & 31;
    const int g   = lane >> 2, tq = lane & 3;
    const int wm  = w & 3, wn = w >> 2;
    const int bm  = blockIdx.y * 128, bn = blockIdx.x * 128;
    const int nck = K >> 5;

    float c[2][8][4];
    #pragma unroll
    for (int mt = 0; mt < 2; mt++)
        #pragma unroll
        for (int nt = 0; nt < 8; nt++)
            #pragma unroll
            for (int j = 0; j < 4; j++) c[mt][nt][j] = 0.f;

    auto stage_load = [&](int ck, int st) {
        const unsigned abase = smem_base + (unsigned)(st * AST) * 4u;
        const unsigned bbase = smem_base + (unsigned)(3*AST + st * BST) * 4u;
        #pragma unroll
        for (int i = 0; i < 4; i++) {
            int idx = tid + 256 * i;
            int m = idx >> 3, c4 = idx & 7;
            cpasync16(abase + (unsigned)(m * 36 + c4 * 4) * 4u,
                      A + (size_t)(bm + m) * K + ck * 32 + c4 * 4);
        }
        #pragma unroll
        for (int i = 0; i < 4; i++) {
            int idx = tid + 256 * i;
            int kr = idx >> 5, c4 = idx & 31;
            cpasync16(bbase + (unsigned)(kr * 132 + c4 * 4) * 4u,
                      B + (size_t)(ck * 32 + kr) * N + bn + c4 * 4);
        }
    };

    stage_load(0, 0);
    asm volatile("cp.async.commit_group;" ::: "memory");
    stage_load(1, 1);
    asm volatile("cp.async.commit_group;" ::: "memory");

    for (int ck = 0; ck < nck; ck++) {
        asm volatile("cp.async.wait_group 1;" ::: "memory");
        __syncthreads();
        if (ck + 2 < nck) stage_load(ck + 2, (ck + 2) % 3);
        asm volatile("cp.async.commit_group;" ::: "memory");

        const int st = ck % 3;
        const float* Ast = As + st * AST;
        const float* Bst = Bs + st * BST;
        #pragma unroll
        for (int ks = 0; ks < 4; ks++) {
            unsigned a[2][4], b[8][2];
            #pragma unroll
            for (int mt = 0; mt < 2; mt++) {
                const int r0 = wm * 32 + g + mt * 16;
                float v0 = Ast[r0 * 36 + ks * 8 + tq];
                float v1 = Ast[(r0 + 8) * 36 + ks * 8 + tq];
                float v2 = Ast[r0 * 36 + ks * 8 + tq + 4];
                float v3 = Ast[(r0 + 8) * 36 + ks * 8 + tq + 4];
                a[mt][0] = CVTA ? f2tf32(v0) : __float_as_uint(v0);
                a[mt][1] = CVTA ? f2tf32(v1) : __float_as_uint(v1);
                a[mt][2] = CVTA ? f2tf32(v2) : __float_as_uint(v2);
                a[mt][3] = CVTA ? f2tf32(v3) : __float_as_uint(v3);
            }
            const int bn0 = wn * 64 + g;
            #pragma unroll
            for (int nt = 0; nt < 8; nt++) {
                float u0 = Bst[(ks * 8 + tq) * 132 + bn0 + nt * 8];
                float u1 = Bst[(ks * 8 + tq + 4) * 132 + bn0 + nt * 8];
                b[nt][0] = CVTB ? f2tf32(u0) : __float_as_uint(u0);
                b[nt][1] = CVTB ? f2tf32(u1) : __float_as_uint(u1);
            }
            #pragma unroll
            for (int mt = 0; mt < 2; mt++)
                #pragma unroll
                for (int nt = 0; nt < 8; nt++)
                    asm volatile(
                        "mma.sync.aligned.m16n8k8.row.col.f32.tf32.tf32.f32 "
                        "{%0,%1,%2,%3}, {%4,%5,%6,%7}, {%8,%9}, {%0,%1,%2,%3};"
                        : "+f"(c[mt][nt][0]), "+f"(c[mt][nt][1]),
                          "+f"(c[mt][nt][2]), "+f"(c[mt][nt][3])
                        : "r"(a[mt][0]), "r"(a[mt][1]), "r"(a[mt][2]), "r"(a[mt][3]),
                          "r"(b[nt][0]), "r"(b[nt][1]));
        }
        __syncthreads();
    }

    #pragma unroll
    for (int mt = 0; mt < 2; mt++) {
        int row = bm + wm * 32 + mt * 16 + g;
        #pragma unroll
        for (int nt = 0; nt < 8; nt++) {
            int col = bn + wn * 64 + nt * 8 + tq * 2;
            float b0 = 0.f, b1 = 0.f;
            if (bias) { b0 = bias[col]; b1 = bias[col + 1]; }
            float o00 = c[mt][nt][0] + b0, o01 = c[mt][nt][1] + b1;
            float o10 = c[mt][nt][2] + b0, o11 = c[mt][nt][3] + b1;
            *(float2*)(C + (size_t)row * N + col)       = make_float2(o00, o01);
            *(float2*)(C + (size_t)(row + 8) * N + col) = make_float2(o10, o11);
            if (Cr) {
                *(float2*)(Cr + (size_t)row * N + col) =
                    make_float2(__uint_as_float(f2tf32(o00)), __uint_as_float(f2tf32(o01)));
                *(float2*)(Cr + (size_t)(row + 8) * N + col) =
                    make_float2(__uint_as_float(f2tf32(o10)), __uint_as_float(f2tf32(o11)));
            }
        }
    }
}

// ================= register-staged TF32 GEMM, B in [N,K] (for q@p^T) =================
#define GSMEM_BYTES (2 * 32 * 132 * 4 * 2)

__global__ void __launch_bounds__(256, 1) gemm_nt_tf32(
    const float* __restrict__ A, const float* __restrict__ B,
    float* __restrict__ C, int M, int N, int K)
{
    extern __shared__ unsigned smem_u[];
    unsigned (*As)[32][132] = reinterpret_cast<unsigned(*)[32][132]>(smem_u);
    unsigned (*Bs)[32][132] = reinterpret_cast<unsigned(*)[32][132]>(smem_u + 2*32*132);

    const int tid = threadIdx.x;
    const int w   = tid >> 5, lane = tid & 31;
    const int g   = lane >> 2, tq = lane & 3;
    const int wm  = w & 3, wn = w >> 2;
    const int bm  = blockIdx.y * 128, bn = blockIdx.x * 128;
    const int nck = K >> 5;

    float4 av[4], bv[4];
    float c[2][8][4];
    #pragma unroll
    for (int mt = 0; mt < 2; mt++)
        #pragma unroll
        for (int nt = 0; nt < 8; nt++)
            #pragma unroll
            for (int j = 0; j < 4; j++) c[mt][nt][j] = 0.f;

    for (int ck = 0; ck <= nck; ck++) {
        if (ck < nck) {
            #pragma unroll
            for (int i = 0; i < 4; i++) {
                int wt = w * 4 + i;
                int c4 = wt & 7;
                int r  = ((wt & 24) << 2) + lane;
                av[i] = *(const float4*)(A + (size_t)(bm + r) * K + ck * 32 + c4 * 4);
                bv[i] = *(const float4*)(B + (size_t)(bn + r) * K + ck * 32 + c4 * 4);
            }
        }
        if (ck > 0) {
            const int cb = (ck - 1) & 1;
            #pragma unroll
            for (int s = 0; s < 4; s++) {
                unsigned a[2][4], b[8][2];
                const unsigned* A0 = As[cb][s * 8 + tq];
                const unsigned* A4 = As[cb][s * 8 + tq + 4];
                const int am = wm * 32 + g;
                #pragma unroll
                for (int mt = 0; mt < 2; mt++) {
                    a[mt][0] = A0[am + mt * 16];
                    a[mt][1] = A0[am + mt * 16 + 8];
                    a[mt][2] = A4[am + mt * 16];
                    a[mt][3] = A4[am + mt * 16 + 8];
                }
                const unsigned* B0 = Bs[cb][s * 8 + tq];
                const unsigned* B4 = Bs[cb][s * 8 + tq + 4];
                const int bn0 = wn * 64 + g;
                #pragma unroll
                for (int nt = 0; nt < 8; nt++) {
                    b[nt][0] = B0[bn0 + nt * 8];
                    b[nt][1] = B4[bn0 + nt * 8];
                }
                #pragma unroll
                for (int mt = 0; mt < 2; mt++)
                    #pragma unroll
                    for (int nt = 0; nt < 8; nt++)
                        asm volatile(
                            "mma.sync.aligned.m16n8k8.row.col.f32.tf32.tf32.f32 "
                            "{%0,%1,%2,%3}, {%4,%5,%6,%7}, {%8,%9}, {%0,%1,%2,%3};"
                            : "+f"(c[mt][nt][0]), "+f"(c[mt][nt][1]),
                              "+f"(c[mt][nt][2]), "+f"(c[mt][nt][3])
                            : "r"(a[mt][0]), "r"(a[mt][1]), "r"(a[mt][2]), "r"(a[mt][3]),
                              "r"(b[nt][0]), "r"(b[nt][1]));
            }
        }
        if (ck < nck) {
            const int sb = ck & 1;
            #pragma unroll
            for (int i = 0; i < 4; i++) {
                int wt = w * 4 + i;
                int c4 = wt & 7;
                int r  = ((wt & 24) << 2) + lane;
                As[sb][c4 * 4 + 0][r] = f2tf32(av[i].x);
                As[sb][c4 * 4 + 1][r] = f2tf32(av[i].y);
                As[sb][c4 * 4 + 2][r] = f2tf32(av[i].z);
                As[sb][c4 * 4 + 3][r] = f2tf32(av[i].w);
                Bs[sb][c4 * 4 + 0][r] = f2tf32(bv[i].x);
                Bs[sb][c4 * 4 + 1][r] = f2tf32(bv[i].y);
                Bs[sb][c4 * 4 + 2][r] = f2tf32(bv[i].z);
                Bs[sb][c4 * 4 + 3][r] = f2tf32(bv[i].w);
            }
        }
        __syncthreads();
    }

    #pragma unroll
    for (int mt = 0; mt < 2; mt++) {
        int row = bm + wm * 32 + mt * 16 + g;
        #pragma unroll
        for (int nt = 0; nt < 8; nt++) {
            int col = bn + wn * 64 + nt * 8 + tq * 2;
            *(float2*)(C + (size_t)row * N + col) =
                make_float2(c[mt][nt][0], c[mt][nt][1]);
            *(float2*)(C + (size_t)(row + 8) * N + col) =
                make_float2(c[mt][nt][2], c[mt][nt][3]);
        }
    }
}

// ---------------- block reduction helpers (blockDim == 256) ----------------
__device__ __forceinline__ float blk_sum256(float v, float* red8) {
    int tid = threadIdx.x, lane = tid & 31, w = tid >> 5;
    #pragma unroll
    for (int o = 16; o; o >>= 1) v += __shfl_xor_sync(0xffffffffu, v, o);
    __syncthreads();
    if (lane == 0) red8[w] = v;
    __syncthreads();
    if (tid == 0) { float t = 0.f; for (int k = 0; k < 8; k++) t += red8[k]; red8[0] = t; }
    __syncthreads();
    return red8[0];
}

__device__ __forceinline__ float blk_max256(float v, float* red8) {
    int tid = threadIdx.x, lane = tid & 31, w = tid >> 5;
    #pragma unroll
    for (int o = 16; o; o >>= 1) v = fmaxf(v, __shfl_xor_sync(0xffffffffu, v, o));
    __syncthreads();
    if (lane == 0) red8[w] = v;
    __syncthreads();
    if (tid == 0) { float t = red8[0]; for (int k = 1; k < 8; k++) t = fmaxf(t, red8[k]); red8[0] = t; }
    __syncthreads();
    return red8[0];
}

// ---------------- misc kernels ----------------
__global__ void copy_f4(const float4* __restrict__ src, float4* __restrict__ dst, int n4) {
    int i = blockIdx.x * blockDim.x + threadIdx.x;
    if (i < n4) dst[i] = src[i];
}

// round-to-tf32 elementwise (vectorized)
__global__ void round_f4(const float4* __restrict__ src, float4* __restrict__ dst, int n4) {
    int i = blockIdx.x * blockDim.x + threadIdx.x;
    if (i < n4) {
        float4 v = src[i];
        dst[i] = make_float4(__uint_as_float(f2tf32(v.x)), __uint_as_float(f2tf32(v.y)),
                             __uint_as_float(f2tf32(v.z)), __uint_as_float(f2tf32(v.w)));
    }
}

// dst[l][f][c] = rna_tf32(gatW[l][h][f][o]), c = h*128+o  ->  [K][N] pre-rounded
__global__ void reorder_gatw_r(const float* __restrict__ src, float* __restrict__ dst) {
    int idx = blockIdx.x * 256 + threadIdx.x;   // covers NL*ED*GH = 3M
    int l = idx >> 20, r = idx & 1048575;
    int f = r >> 10, c = r & 1023, h = c >> 7, o = c & 127;
    float v = src[(size_t)l * (NH*ED*HD) + ((size_t)h * 1024 + f) * 128 + o];
    dst[idx] = __uint_as_float(f2tf32(v));
}

// ---------------- CSR build (adj > 0) ----------------
__global__ void csr_count(const float* __restrict__ adj, int* __restrict__ deg) {
    int w = (blockIdx.x * blockDim.x + threadIdx.x) >> 5;
    int lane = threadIdx.x & 31;
    if (w >= NN_) return;
    const float* row = adj + (size_t)w * NN_;
    int cnt = 0;
    for (int c = 0; c < NN_/32; c++) {
        unsigned m = __ballot_sync(0xffffffffu, row[c*32 + lane] > 0.f);
        cnt += __popc(m);
    }
    if (lane == 0) deg[w] = cnt;
}

__global__ void csr_scan(const int* __restrict__ deg, int* __restrict__ rowptr) {
    __shared__ int ps[128];
    int t = threadIdx.x; // 128
    int s = 0;
    for (int i = 0; i < 16; i++) s += deg[t*16 + i];
    ps[t] = s;
    __syncthreads();
    if (t == 0) { int run = 0; for (int i = 0; i < 128; i++) { int v = ps[i]; ps[i] = run; run += v; } }
    __syncthreads();
    int run = ps[t];
    for (int i = 0; i < 16; i++) { rowptr[t*16 + i] = run; run += deg[t*16 + i]; }
    if (t == 127) rowptr[NN_] = run;
}

__global__ void csr_fill(const float* __restrict__ adj, const int* __restrict__ rowptr,
                         int* __restrict__ colidx) {
    int w = (blockIdx.x * blockDim.x + threadIdx.x) >> 5;
    int lane = threadIdx.x & 31;
    if (w >= NN_) return;
    const float* row = adj + (size_t)w * NN_;
    int base = rowptr[w];
    for (int c = 0; c < NN_/32; c++) {
        int j = c*32 + lane;
        bool p = row[j] > 0.f;
        unsigned m = __ballot_sync(0xffffffffu, p);
        if (p) colidx[base + __popc(m & ((1u << lane) - 1u))] = j;
        base += __popc(m);
    }
}

// ---------------- GAT pieces ----------------
__global__ void gat_scores(const float* __restrict__ Wh, const float* __restrict__ a1,
                           const float* __restrict__ a2, float* __restrict__ s1,
                           float* __restrict__ s2) {
    int n = blockIdx.x;
    int w = threadIdx.x >> 5, lane = threadIdx.x & 31;  // 8 warps = 8 heads
    const float* wr  = Wh + (size_t)n * GH + w * HD;
    const float* a1p = a1 + w * HD;
    const float* a2p = a2 + w * HD;
    float v1 = 0.f, v2 = 0.f;
    for (int o = lane; o < HD; o += 32) { float x = wr[o]; v1 += x * a1p[o]; v2 += x * a2p[o]; }
    #pragma unroll
    for (int o = 16; o; o >>= 1) {
        v1 += __shfl_xor_sync(0xffffffffu, v1, o);
        v2 += __shfl_xor_sync(0xffffffffu, v2, o);
    }
    if (lane == 0) { s1[n*NH + w] = v1; s2[n*NH + w] = v2; }
}

__global__ void __launch_bounds__(256) gat_aggregate(
    const float* __restrict__ Wh, const float* __restrict__ s1,
    const float* __restrict__ s2, const int* __restrict__ rowptr,
    const int* __restrict__ colidx, float* __restrict__ out)
{
    const int i = blockIdx.x, tid = threadIdx.x, lane = tid & 31, w = tid >> 5;
    __shared__ float s1sh[8], mh[8], zh[8];
    __shared__ float wred[8][8];
    __shared__ float att[128*8];
    __shared__ int   jsh[128];

    if (tid < 8) s1sh[tid] = s1[i*NH + tid];
    const int base = rowptr[i];
    const int deg  = rowptr[i+1] - base;
    __syncthreads();

    float lm[8];
    #pragma unroll
    for (int h = 0; h < 8; h++) lm[h] = -1e30f;
    for (int jj = tid; jj < deg; jj += 256) {
        int j = colidx[base + jj];
        #pragma unroll
        for (int h = 0; h < 8; h++) {
            float e = s1sh[h] + s2[j*NH + h];
            e = e > 0.f ? e : 0.2f * e;
            lm[h] = fmaxf(lm[h], e);
        }
    }
    #pragma unroll
    for (int h = 0; h < 8; h++) {
        #pragma unroll
        for (int o = 16; o; o >>= 1) lm[h] = fmaxf(lm[h], __shfl_xor_sync(0xffffffffu, lm[h], o));
    }
    if (lane == 0) {
        for (int h = 0; h < 8; h++) wred[w][h] = lm[h];
    }
    __syncthreads();
    if (tid < 8) {
        float m = wred[0][tid];
        for (int ww = 1; ww < 8; ww++) m = fmaxf(m, wred[ww][tid]);
        mh[tid] = m;
    }
    __syncthreads();

    float ls[8];
    #pragma unroll
    for (int h = 0; h < 8; h++) ls[h] = 0.f;
    for (int jj = tid; jj < deg; jj += 256) {
        int j = colidx[base + jj];
        #pragma unroll
        for (int h = 0; h < 8; h++) {
            float e = s1sh[h] + s2[j*NH + h];
            e = e > 0.f ? e : 0.2f * e;
            ls[h] += expf(e - mh[h]);
        }
    }
    #pragma unroll
    for (int h = 0; h < 8; h++) {
        #pragma unroll
        for (int o = 16; o; o >>= 1) ls[h] += __shfl_xor_sync(0xffffffffu, ls[h], o);
    }
    __syncthreads();
    if (lane == 0) {
        for (int h = 0; h < 8; h++) wred[w][h] = ls[h];
    }
    __syncthreads();
    if (tid < 8) {
        float s = 0.f;
        for (int ww = 0; ww < 8; ww++) s += wred[ww][tid];
        zh[tid] = s;
    }
    __syncthreads();

    float acc0 = 0.f, acc1 = 0.f, acc2 = 0.f, acc3 = 0.f;
    const int c0 = tid, c1 = tid + 256, c2 = tid + 512, c3 = tid + 768;
    const int h0 = c0 >> 7, h1 = c1 >> 7, h2 = c2 >> 7, h3 = c3 >> 7;
    for (int cs = 0; cs < deg; cs += 128) {
        const int nck = min(128, deg - cs);
        __syncthreads();
        for (int idx = tid; idx < nck; idx += 256) jsh[idx] = colidx[base + cs + idx];
        for (int idx = tid; idx < nck * 8; idx += 256) {
            int jj = idx >> 3, h = idx & 7;
            int j = colidx[base + cs + jj];
            float e = s1sh[h] + s2[j*NH + h];
            e = e > 0.f ? e : 0.2f * e;
            att[idx] = expf(e - mh[h]) / zh[h];
        }
        __syncthreads();
        int jj = 0;
        for (; jj + 1 < nck; jj += 2) {
            const float* wr0 = Wh + (size_t)jsh[jj] * GH;
            const float* at0 = att + jj * 8;
            const float* wr1 = Wh + (size_t)jsh[jj+1] * GH;
            const float* at1 = att + (jj+1) * 8;
            acc0 += at0[h0] * wr0[c0] + at1[h0] * wr1[c0];
            acc1 += at0[h1] * wr0[c1] + at1[h1] * wr1[c1];
            acc2 += at0[h2] * wr0[c2] + at1[h2] * wr1[c2];
            acc3 += at0[h3] * wr0[c3] + at1[h3] * wr1[c3];
        }
        if (jj < nck) {
            const float* wr = Wh + (size_t)jsh[jj] * GH;
            const float* at = att + jj * 8;
            acc0 += at[h0] * wr[c0];
            acc1 += at[h1] * wr[c1];
            acc2 += at[h2] * wr[c2];
            acc3 += at[h3] * wr[c3];
        }
    }
    float* orow = out + (size_t)i * GH;
    orow[c0] = acc0; orow[c1] = acc1; orow[c2] = acc2; orow[c3] = acc3;
}

// ---------------- LN + activation ----------------
__global__ void ln_act(const float* __restrict__ X, const float* __restrict__ g,
                       const float* __restrict__ b, float* __restrict__ out, int mode) {
    __shared__ float red8[8];
    int row = blockIdx.x, tid = threadIdx.x;
    const float* xr = X + (size_t)row * 1024;
    float v[4];
    #pragma unroll
    for (int k = 0; k < 4; k++) v[k] = xr[tid + 256*k];
    float s = v[0] + v[1] + v[2] + v[3];
    s = blk_sum256(s, red8);
    float mu = s * (1.f/1024.f);
    float q = 0.f;
    #pragma unroll
    for (int k = 0; k < 4; k++) { float d = v[k] - mu; q += d * d; }
    q = blk_sum256(q, red8);
    float rstd = rsqrtf(q * (1.f/1024.f) + 1e-5f);
    float* orow = out + (size_t)row * 1024;
    #pragma unroll
    for (int k = 0; k < 4; k++) {
        int c = tid + 256*k;
        float y = (v[k] - mu) * rstd * g[c] + b[c];
        if (mode == 0) {
            orow[c] = y * 0.5f * (1.f + erff(y * 0.70710678118654752f));
        } else {
            float e = y > 0.f ? y : expm1f(y);
            orow[c] += e;
        }
    }
}

__global__ void l2norm_rows(const float* __restrict__ X, float* __restrict__ out) {
    __shared__ float red8[8];
    int row = blockIdx.x, tid = threadIdx.x;
    const float* xr = X + (size_t)row * 1024;
    float v[4];
    #pragma unroll
    for (int k = 0; k < 4; k++) v[k] = xr[tid + 256*k];
    float q = v[0]*v[0] + v[1]*v[1] + v[2]*v[2] + v[3]*v[3];
    q = blk_sum256(q, red8);
    float inv = 1.f / fmaxf(sqrtf(q), 1e-12f);
    float* orow = out + (size_t)row * 1024;
    #pragma unroll
    for (int k = 0; k < 4; k++) orow[tid + 256*k] = v[k] * inv;
}

__global__ void rowdot(const float* __restrict__ A, const float* __restrict__ B,
                       float* __restrict__ out) {
    __shared__ float red8[8];
    int row = blockIdx.x, tid = threadIdx.x;
    const float* ar = A + (size_t)row * 1024;
    const float* br = B + (size_t)row * 1024;
    float s = 0.f;
    #pragma unroll
    for (int k = 0; k < 4; k++) { int c = tid + 256*k; s += ar[c] * br[c]; }
    s = blk_sum256(s, red8);
    if (tid == 0) out[row] = s;
}

__global__ void lse_rows(const float* __restrict__ neg, float* __restrict__ infoRow) {
    __shared__ float red8[8];
    int row = blockIdx.x, tid = threadIdx.x;
    const float* r = neg + (size_t)row * 1024;
    float v[4];
    #pragma unroll
    for (int k = 0; k < 4; k++) v[k] = r[tid + 256*k] * 20.0f;  // 1/TEMP
    float m = fmaxf(fmaxf(v[0], v[1]), fmaxf(v[2], v[3]));
    m = blk_max256(m, red8);
    float s = 0.f;
    #pragma unroll
    for (int k = 0; k < 4; k++) s += expf(v[k] - m);
    s = blk_sum256(s, red8);
    if (tid == 0) {
        float pos = r[row] * 20.0f;
        float lse = m + logf(expf(pos - m) + s);
        infoRow[row] = lse - pos;
    }
}

__global__ void finalize_k(const float* __restrict__ infoRow, const float* __restrict__ lapRow,
                           float* __restrict__ out, int out_size) {
    __shared__ float ri[32], rl[32];
    int tid = threadIdx.x, lane = tid & 31, w = tid >> 5; // 1024 threads
    float vi = infoRow[tid];
    float vl = lapRow[tid] + lapRow[tid + 1024];
    #pragma unroll
    for (int o = 16; o; o >>= 1) {
        vi += __shfl_xor_sync(0xffffffffu, vi, o);
        vl += __shfl_xor_sync(0xffffffffu, vl, o);
    }
    if (lane == 0) { ri[w] = vi; rl[w] = vl; }
    __syncthreads();
    if (tid == 0) {
        float si = 0.f, sl = 0.f;
        for (int k = 0; k < 32; k++) { si += ri[k]; sl += rl[k]; }
        float info = si / 1024.f;
        float lap  = sl / 2048.f;
        float total = info + 0.1f * lap;
        out[0] = total;
        if (out_size > 1) out[1] = info;
        if (out_size > 2) out[2] = lap;
    }
}

// ---------------- host ----------------
extern "C" void kernel_launch(void* const* d_in, const int* in_sizes, int n_in,
                              void* d_out, int out_size) {
    const float* query = (const float*)d_in[0];
    const float* docs  = (const float*)d_in[1];
    const float* nodes = (const float*)d_in[2];
    const float* adj   = (const float*)d_in[3];
    const float* lapl  = (const float*)d_in[4];
    const float* qW1 = (const float*)d_in[5];  const float* qb1 = (const float*)d_in[6];
    const float* qg  = (const float*)d_in[7];  const float* qbt = (const float*)d_in[8];
    const float* qW2 = (const float*)d_in[9];  const float* qb2 = (const float*)d_in[10];
    const float* dW1 = (const float*)d_in[11]; const float* db1 = (const float*)d_in[12];
    const float* dg  = (const float*)d_in[13]; const float* dbt = (const float*)d_in[14];
    const float* dW2 = (const float*)d_in[15]; const float* db2 = (const float*)d_in[16];
    const float* gatW = (const float*)d_in[17];
    const float* a1   = (const float*)d_in[18];
    const float* a2   = (const float*)d_in[19];
    const float* ln_g = (const float*)d_in[20];
    const float* ln_b = (const float*)d_in[21];
    const float* poW  = (const float*)d_in[22];
    const float* pob  = (const float*)d_in[23];

    void* tp;
    float *px, *pWh, *ps1, *ps2, *ph, *pG, *pGr, *pLG;
    float *pt1, *pt2, *pt3, *pt4, *pq, *pp, *pneg, *pinfo, *plap;
    float *pWr, *ppoWr, *plaplr;
    int *pdeg, *prowptr, *pcolidx;
    cudaGetSymbolAddress(&tp, g_x);   px  = (float*)tp;
    cudaGetSymbolAddress(&tp, g_Wh);  pWh = (float*)tp;
    cudaGetSymbolAddress(&tp, g_s1);  ps1 = (float*)tp;
    cudaGetSymbolAddress(&tp, g_s2);  ps2 = (float*)tp;
    cudaGetSymbolAddress(&tp, g_h);   ph  = (float*)tp;
    cudaGetSymbolAddress(&tp, g_G);   pG  = (float*)tp;
    cudaGetSymbolAddress(&tp, g_Gr);  pGr = (float*)tp;
    cudaGetSymbolAddress(&tp, g_LG);  pLG = (float*)tp;
    cudaGetSymbolAddress(&tp, g_t1);  pt1 = (float*)tp;
    cudaGetSymbolAddress(&tp, g_t2);  pt2 = (float*)tp;
    cudaGetSymbolAddress(&tp, g_t3);  pt3 = (float*)tp;
    cudaGetSymbolAddress(&tp, g_t4);  pt4 = (float*)tp;
    cudaGetSymbolAddress(&tp, g_q);   pq  = (float*)tp;
    cudaGetSymbolAddress(&tp, g_p);   pp  = (float*)tp;
    cudaGetSymbolAddress(&tp, g_neg); pneg = (float*)tp;
    cudaGetSymbolAddress(&tp, g_infoRow); pinfo = (float*)tp;
    cudaGetSymbolAddress(&tp, g_lapRow);  plap  = (float*)tp;
    cudaGetSymbolAddress(&tp, g_Wr);    pWr    = (float*)tp;
    cudaGetSymbolAddress(&tp, g_poWr);  ppoWr  = (float*)tp;
    cudaGetSymbolAddress(&tp, g_laplr); plaplr = (float*)tp;
    cudaGetSymbolAddress(&tp, g_deg);     pdeg    = (int*)tp;
    cudaGetSymbolAddress(&tp, g_rowptr);  prowptr = (int*)tp;
    cudaGetSymbolAddress(&tp, g_colidx);  pcolidx = (int*)tp;

    static cudaStream_t sQ = nullptr, sD = nullptr, sC = nullptr;
    static cudaEvent_t evRoot, evQ, evD, evC, evW;
    if (!sQ) {
        cudaStreamCreateWithFlags(&sQ, cudaStreamNonBlocking);
        cudaStreamCreateWithFlags(&sD, cudaStreamNonBlocking);
        cudaStreamCreateWithFlags(&sC, cudaStreamNonBlocking);
        cudaEventCreateWithFlags(&evRoot, cudaEventDisableTiming);
        cudaEventCreateWithFlags(&evQ, cudaEventDisableTiming);
        cudaEventCreateWithFlags(&evD, cudaEventDisableTiming);
        cudaEventCreateWithFlags(&evC, cudaEventDisableTiming);
        cudaEventCreateWithFlags(&evW, cudaEventDisableTiming);
        cudaFuncSetAttribute(gemm_ca<true,true>,  cudaFuncAttributeMaxDynamicSharedMemorySize, GC_SMEM);
        cudaFuncSetAttribute(gemm_ca<true,false>, cudaFuncAttributeMaxDynamicSharedMemorySize, GC_SMEM);
        cudaFuncSetAttribute(gemm_ca<false,false>,cudaFuncAttributeMaxDynamicSharedMemorySize, GC_SMEM);
        cudaFuncSetAttribute(gemm_nt_tf32, cudaFuncAttributeMaxDynamicSharedMemorySize, GSMEM_BYTES);
    }

    // fork point
    cudaEventRecord(evRoot, 0);
    cudaStreamWaitEvent(sQ, evRoot, 0);
    cudaStreamWaitEvent(sD, evRoot, 0);
    cudaStreamWaitEvent(sC, evRoot, 0);

    // ---- stream sC: pre-round weights (gatW reorder+round, poW, lapl), then CSR ----
    reorder_gatw_r<<<(NL*ED*GH)/256, 256, 0, sC>>>(gatW, pWr);
    cudaEventRecord(evW, sC);
    round_f4<<<(GH*ED/4 + 255)/256, 256, 0, sC>>>((const float4*)poW, (float4*)ppoWr, GH*ED/4);
    round_f4<<<(NN_*NN_/4 + 255)/256, 256, 0, sC>>>((const float4*)lapl, (float4*)plaplr, NN_*NN_/4);
    csr_count<<<NN_*32/256, 256, 0, sC>>>(adj, pdeg);
    csr_scan<<<1, 128, 0, sC>>>(pdeg, prowptr);
    csr_fill<<<NN_*32/256, 256, 0, sC>>>(adj, prowptr, pcolidx);
    cudaEventRecord(evC, sC);

    // ---- stream sD: doc MLP -> p ----
    gemm_ca<true,true><<<dim3(ED/128, BB/128), 256, GC_SMEM, sD>>>(docs, dW1, db1, pt3, nullptr, BB, ED, ED);
    ln_act<<<BB, 256, 0, sD>>>(pt3, dg, dbt, pt4, 0);
    gemm_ca<true,true><<<dim3(ED/128, BB/128), 256, GC_SMEM, sD>>>(pt4, dW2, db2, pt3, nullptr, BB, ED, ED);
    l2norm_rows<<<BB, 256, 0, sD>>>(pt3, pp);
    cudaEventRecord(evD, sD);

    // ---- stream sQ: query MLP -> q, then neg + lse ----
    gemm_ca<true,true><<<dim3(ED/128, BB/128), 256, GC_SMEM, sQ>>>(query, qW1, qb1, pt1, nullptr, BB, ED, ED);
    ln_act<<<BB, 256, 0, sQ>>>(pt1, qg, qbt, pt2, 0);
    gemm_ca<true,true><<<dim3(ED/128, BB/128), 256, GC_SMEM, sQ>>>(pt2, qW2, qb2, pt1, nullptr, BB, ED, ED);
    l2norm_rows<<<BB, 256, 0, sQ>>>(pt1, pq);
    cudaStreamWaitEvent(sQ, evD, 0);
    gemm_nt_tf32<<<dim3(BB/128, BB/128), 256, GSMEM_BYTES, sQ>>>(pq, pp, pneg, BB, BB, ED);
    lse_rows<<<BB, 256, 0, sQ>>>(pneg, pinfo);
    cudaEventRecord(evQ, sQ);

    // ---- default stream: GNN chain ----
    copy_f4<<<(NN_*ED/4 + 255)/256, 256>>>((const float4*)nodes, (float4*)px, NN_*ED/4);
    cudaStreamWaitEvent(0, evW, 0);
    for (int l = 0; l < NL; l++) {
        gemm_ca<true,false><<<dim3(GH/128, NN_/128), 256, GC_SMEM>>>(
            px, pWr + (size_t)l*ED*GH, nullptr, pWh, nullptr, NN_, GH, ED);
        gat_scores<<<NN_, 256>>>(pWh, a1 + l*NH*HD, a2 + l*NH*HD, ps1, ps2);
        if (l == 0) cudaStreamWaitEvent(0, evC, 0);
        gat_aggregate<<<NN_, 256>>>(pWh, ps1, ps2, prowptr, pcolidx, ph);
        ln_act<<<NN_, 256>>>(ph, ln_g + l*GH, ln_b + l*GH, px, 1);
    }
    // G (fp32, for rowdot) + Gr (tf32-rounded, as B of the laplacian GEMM)
    gemm_ca<true,false><<<dim3(ED/128, NN_/128), 256, GC_SMEM>>>(px, ppoWr, pob, pG, pGr, NN_, ED, GH);
    gemm_ca<false,false><<<dim3(ED/128, NN_/128), 256, GC_SMEM>>>(plaplr, pGr, nullptr, pLG, nullptr, NN_, ED, NN_);
    rowdot<<<NN_, 256>>>(pG, pLG, plap);

    // ---- join + finalize ----
    cudaStreamWaitEvent(0, evQ, 0);
    finalize_k<<<1, 1024>>>(pinfo, plap, (float*)d_out, out_size);
}

// round 11
// speedup vs baseline: 3.4524x; 1.0391x over previous
#include <cuda_runtime.h>
#include <cuda_bf16.h>
#include <math.h>

// Problem dims (fixed per reference)
#define ED   1024
#define GH   1024
#define NL   3
#define NH   8
#define HD   128
#define NN_  2048   // graph nodes
#define BB   1024   // batch

// ---------------- scratch (static device globals; no allocation) ----------------
__device__ float g_x [NN_*GH];
__device__ float g_Wh[NN_*GH];
__device__ float g_s1[NN_*NH];
__device__ float g_s2[NN_*NH];
__device__ float g_G [NN_*ED];
__device__ float g_Gr[NN_*ED];
__device__ float g_LG[NN_*ED];
__device__ float g_t1[BB*ED];
__device__ float g_t2[BB*ED];
__device__ float g_t3[BB*ED];
__device__ float g_t4[BB*ED];
__device__ float g_q [BB*ED];
__device__ float g_p [BB*ED];
__device__ float g_neg[BB*BB];
__device__ float g_infoRow[BB];
__device__ float g_lapRow[NN_];
__device__ float g_Wr[NL*ED*GH];      // rounded+reordered gatW (all layers)
__device__ float g_poWr[GH*ED];       // rounded poW
__device__ float g_laplr[NN_*NN_];    // rounded laplacian
__device__ int   g_deg[NN_];
__device__ int   g_rowptr[NN_+1];
__device__ int   g_colidx[NN_*NN_];

__device__ __forceinline__ unsigned f2tf32(float x) {
    unsigned r; asm("cvt.rna.tf32.f32 %0, %1;" : "=r"(r) : "f"(x)); return r;
}
__device__ __forceinline__ unsigned smem_u32(const void* p) {
    unsigned a;
    asm("{ .reg .u64 t; cvta.to.shared.u64 t, %1; cvt.u32.u64 %0, t; }" : "=r"(a) : "l"(p));
    return a;
}
__device__ __forceinline__ void cpasync16(unsigned dst, const void* src) {
    asm volatile("cp.async.cg.shared.global [%0], [%1], 16;" :: "r"(dst), "l"(src));
}

// ================= cp.async 3-stage pipelined TF32 GEMM (B in [K,N]) =================
#define AST (128*36)
#define BST (32*132)
#define GC_SMEM ((3*(AST+BST))*4)

template<bool CVTA, bool CVTB>
__global__ void __launch_bounds__(256, 1) gemm_ca(
    const float* __restrict__ A, const float* __restrict__ B,
    const float* __restrict__ bias, float* __restrict__ C,
    float* __restrict__ Cr,
    int M, int N, int K)
{
    extern __shared__ float sm[];
    const float* As = sm;
    const float* Bs = sm + 3*AST;
    const unsigned smem_base = smem_u32(sm);

    const int tid = threadIdx.x;
    const int w   = tid >> 5, lane = tid & 31;
    const int g   = lane >> 2, tq = lane & 3;
    const int wm  = w & 3, wn = w >> 2;
    const int bm  = blockIdx.y * 128, bn = blockIdx.x * 128;
    const int nck = K >> 5;

    float c[2][8][4];
    #pragma unroll
    for (int mt = 0; mt < 2; mt++)
        #pragma unroll
        for (int nt = 0; nt < 8; nt++)
            #pragma unroll
            for (int j = 0; j < 4; j++) c[mt][nt][j] = 0.f;

    auto stage_load = [&](int ck, int st) {
        const unsigned abase = smem_base + (unsigned)(st * AST) * 4u;
        const unsigned bbase = smem_base + (unsigned)(3*AST + st * BST) * 4u;
        #pragma unroll
        for (int i = 0; i < 4; i++) {
            int idx = tid + 256 * i;
            int m = idx >> 3, c4 = idx & 7;
            cpasync16(abase + (unsigned)(m * 36 + c4 * 4) * 4u,
                      A + (size_t)(bm + m) * K + ck * 32 + c4 * 4);
        }
        #pragma unroll
        for (int i = 0; i < 4; i++) {
            int idx = tid + 256 * i;
            int kr = idx >> 5, c4 = idx & 31;
            cpasync16(bbase + (unsigned)(kr * 132 + c4 * 4) * 4u,
                      B + (size_t)(ck * 32 + kr) * N + bn + c4 * 4);
        }
    };

    stage_load(0, 0);
    asm volatile("cp.async.commit_group;" ::: "memory");
    stage_load(1, 1);
    asm volatile("cp.async.commit_group;" ::: "memory");

    for (int ck = 0; ck < nck; ck++) {
        asm volatile("cp.async.wait_group 1;" ::: "memory");
        __syncthreads();
        if (ck + 2 < nck) stage_load(ck + 2, (ck + 2) % 3);
        asm volatile("cp.async.commit_group;" ::: "memory");

        const int st = ck % 3;
        const float* Ast = As + st * AST;
        const float* Bst = Bs + st * BST;
        #pragma unroll
        for (int ks = 0; ks < 4; ks++) {
            unsigned a[2][4], b[8][2];
            #pragma unroll
            for (int mt = 0; mt < 2; mt++) {
                const int r0 = wm * 32 + g + mt * 16;
                float v0 = Ast[r0 * 36 + ks * 8 + tq];
                float v1 = Ast[(r0 + 8) * 36 + ks * 8 + tq];
                float v2 = Ast[r0 * 36 + ks * 8 + tq + 4];
                float v3 = Ast[(r0 + 8) * 36 + ks * 8 + tq + 4];
                a[mt][0] = CVTA ? f2tf32(v0) : __float_as_uint(v0);
                a[mt][1] = CVTA ? f2tf32(v1) : __float_as_uint(v1);
                a[mt][2] = CVTA ? f2tf32(v2) : __float_as_uint(v2);
                a[mt][3] = CVTA ? f2tf32(v3) : __float_as_uint(v3);
            }
            const int bn0 = wn * 64 + g;
            #pragma unroll
            for (int nt = 0; nt < 8; nt++) {
                float u0 = Bst[(ks * 8 + tq) * 132 + bn0 + nt * 8];
                float u1 = Bst[(ks * 8 + tq + 4) * 132 + bn0 + nt * 8];
                b[nt][0] = CVTB ? f2tf32(u0) : __float_as_uint(u0);
                b[nt][1] = CVTB ? f2tf32(u1) : __float_as_uint(u1);
            }
            #pragma unroll
            for (int mt = 0; mt < 2; mt++)
                #pragma unroll
                for (int nt = 0; nt < 8; nt++)
                    asm volatile(
                        "mma.sync.aligned.m16n8k8.row.col.f32.tf32.tf32.f32 "
                        "{%0,%1,%2,%3}, {%4,%5,%6,%7}, {%8,%9}, {%0,%1,%2,%3};"
                        : "+f"(c[mt][nt][0]), "+f"(c[mt][nt][1]),
                          "+f"(c[mt][nt][2]), "+f"(c[mt][nt][3])
                        : "r"(a[mt][0]), "r"(a[mt][1]), "r"(a[mt][2]), "r"(a[mt][3]),
                          "r"(b[nt][0]), "r"(b[nt][1]));
        }
        __syncthreads();
    }

    #pragma unroll
    for (int mt = 0; mt < 2; mt++) {
        int row = bm + wm * 32 + mt * 16 + g;
        #pragma unroll
        for (int nt = 0; nt < 8; nt++) {
            int col = bn + wn * 64 + nt * 8 + tq * 2;
            float b0 = 0.f, b1 = 0.f;
            if (bias) { b0 = bias[col]; b1 = bias[col + 1]; }
            float o00 = c[mt][nt][0] + b0, o01 = c[mt][nt][1] + b1;
            float o10 = c[mt][nt][2] + b0, o11 = c[mt][nt][3] + b1;
            *(float2*)(C + (size_t)row * N + col)       = make_float2(o00, o01);
            *(float2*)(C + (size_t)(row + 8) * N + col) = make_float2(o10, o11);
            if (Cr) {
                *(float2*)(Cr + (size_t)row * N + col) =
                    make_float2(__uint_as_float(f2tf32(o00)), __uint_as_float(f2tf32(o01)));
                *(float2*)(Cr + (size_t)(row + 8) * N + col) =
                    make_float2(__uint_as_float(f2tf32(o10)), __uint_as_float(f2tf32(o11)));
            }
        }
    }
}

// ================= register-staged TF32 GEMM, B in [N,K] (for q@p^T) =================
#define GSMEM_BYTES (2 * 32 * 132 * 4 * 2)

__global__ void __launch_bounds__(256, 1) gemm_nt_tf32(
    const float* __restrict__ A, const float* __restrict__ B,
    float* __restrict__ C, int M, int N, int K)
{
    extern __shared__ unsigned smem_u[];
    unsigned (*As)[32][132] = reinterpret_cast<unsigned(*)[32][132]>(smem_u);
    unsigned (*Bs)[32][132] = reinterpret_cast<unsigned(*)[32][132]>(smem_u + 2*32*132);

    const int tid = threadIdx.x;
    const int w   = tid >> 5, lane = tid & 31;
    const int g   = lane >> 2, tq = lane & 3;
    const int wm  = w & 3, wn = w >> 2;
    const int bm  = blockIdx.y * 128, bn = blockIdx.x * 128;
    const int nck = K >> 5;

    float4 av[4], bv[4];
    float c[2][8][4];
    #pragma unroll
    for (int mt = 0; mt < 2; mt++)
        #pragma unroll
        for (int nt = 0; nt < 8; nt++)
            #pragma unroll
            for (int j = 0; j < 4; j++) c[mt][nt][j] = 0.f;

    for (int ck = 0; ck <= nck; ck++) {
        if (ck < nck) {
            #pragma unroll
            for (int i = 0; i < 4; i++) {
                int wt = w * 4 + i;
                int c4 = wt & 7;
                int r  = ((wt & 24) << 2) + lane;
                av[i] = *(const float4*)(A + (size_t)(bm + r) * K + ck * 32 + c4 * 4);
                bv[i] = *(const float4*)(B + (size_t)(bn + r) * K + ck * 32 + c4 * 4);
            }
        }
        if (ck > 0) {
            const int cb = (ck - 1) & 1;
            #pragma unroll
            for (int s = 0; s < 4; s++) {
                unsigned a[2][4], b[8][2];
                const unsigned* A0 = As[cb][s * 8 + tq];
                const unsigned* A4 = As[cb][s * 8 + tq + 4];
                const int am = wm * 32 + g;
                #pragma unroll
                for (int mt = 0; mt < 2; mt++) {
                    a[mt][0] = A0[am + mt * 16];
                    a[mt][1] = A0[am + mt * 16 + 8];
                    a[mt][2] = A4[am + mt * 16];
                    a[mt][3] = A4[am + mt * 16 + 8];
                }
                const unsigned* B0 = Bs[cb][s * 8 + tq];
                const unsigned* B4 = Bs[cb][s * 8 + tq + 4];
                const int bn0 = wn * 64 + g;
                #pragma unroll
                for (int nt = 0; nt < 8; nt++) {
                    b[nt][0] = B0[bn0 + nt * 8];
                    b[nt][1] = B4[bn0 + nt * 8];
                }
                #pragma unroll
                for (int mt = 0; mt < 2; mt++)
                    #pragma unroll
                    for (int nt = 0; nt < 8; nt++)
                        asm volatile(
                            "mma.sync.aligned.m16n8k8.row.col.f32.tf32.tf32.f32 "
                            "{%0,%1,%2,%3}, {%4,%5,%6,%7}, {%8,%9}, {%0,%1,%2,%3};"
                            : "+f"(c[mt][nt][0]), "+f"(c[mt][nt][1]),
                              "+f"(c[mt][nt][2]), "+f"(c[mt][nt][3])
                            : "r"(a[mt][0]), "r"(a[mt][1]), "r"(a[mt][2]), "r"(a[mt][3]),
                              "r"(b[nt][0]), "r"(b[nt][1]));
            }
        }
        if (ck < nck) {
            const int sb = ck & 1;
            #pragma unroll
            for (int i = 0; i < 4; i++) {
                int wt = w * 4 + i;
                int c4 = wt & 7;
                int r  = ((wt & 24) << 2) + lane;
                As[sb][c4 * 4 + 0][r] = f2tf32(av[i].x);
                As[sb][c4 * 4 + 1][r] = f2tf32(av[i].y);
                As[sb][c4 * 4 + 2][r] = f2tf32(av[i].z);
                As[sb][c4 * 4 + 3][r] = f2tf32(av[i].w);
                Bs[sb][c4 * 4 + 0][r] = f2tf32(bv[i].x);
                Bs[sb][c4 * 4 + 1][r] = f2tf32(bv[i].y);
                Bs[sb][c4 * 4 + 2][r] = f2tf32(bv[i].z);
                Bs[sb][c4 * 4 + 3][r] = f2tf32(bv[i].w);
            }
        }
        __syncthreads();
    }

    #pragma unroll
    for (int mt = 0; mt < 2; mt++) {
        int row = bm + wm * 32 + mt * 16 + g;
        #pragma unroll
        for (int nt = 0; nt < 8; nt++) {
            int col = bn + wn * 64 + nt * 8 + tq * 2;
            *(float2*)(C + (size_t)row * N + col) =
                make_float2(c[mt][nt][0], c[mt][nt][1]);
            *(float2*)(C + (size_t)(row + 8) * N + col) =
                make_float2(c[mt][nt][2], c[mt][nt][3]);
        }
    }
}

// ---------------- block reduction helpers (blockDim == 256) ----------------
__device__ __forceinline__ float blk_sum256(float v, float* red8) {
    int tid = threadIdx.x, lane = tid & 31, w = tid >> 5;
    #pragma unroll
    for (int o = 16; o; o >>= 1) v += __shfl_xor_sync(0xffffffffu, v, o);
    __syncthreads();
    if (lane == 0) red8[w] = v;
    __syncthreads();
    if (tid == 0) { float t = 0.f; for (int k = 0; k < 8; k++) t += red8[k]; red8[0] = t; }
    __syncthreads();
    return red8[0];
}

__device__ __forceinline__ float blk_max256(float v, float* red8) {
    int tid = threadIdx.x, lane = tid & 31, w = tid >> 5;
    #pragma unroll
    for (int o = 16; o; o >>= 1) v = fmaxf(v, __shfl_xor_sync(0xffffffffu, v, o));
    __syncthreads();
    if (lane == 0) red8[w] = v;
    __syncthreads();
    if (tid == 0) { float t = red8[0]; for (int k = 1; k < 8; k++) t = fmaxf(t, red8[k]); red8[0] = t; }
    __syncthreads();
    return red8[0];
}

// ---------------- misc kernels ----------------
__global__ void round_f4(const float4* __restrict__ src, float4* __restrict__ dst, int n4) {
    int i = blockIdx.x * blockDim.x + threadIdx.x;
    if (i < n4) {
        float4 v = src[i];
        dst[i] = make_float4(__uint_as_float(f2tf32(v.x)), __uint_as_float(f2tf32(v.y)),
                             __uint_as_float(f2tf32(v.z)), __uint_as_float(f2tf32(v.w)));
    }
}

// dst[f][c] = rna_tf32(gatW_layer[h][f][o]), c = h*128+o  (one layer per launch)
__global__ void reorder_gatw_r(const float* __restrict__ src, float* __restrict__ dst) {
    int idx = blockIdx.x * 256 + threadIdx.x;   // covers ED*GH = 1M
    int f = idx >> 10, c = idx & 1023, h = c >> 7, o = c & 127;
    float v = src[((size_t)h * 1024 + f) * 128 + o];
    dst[idx] = __uint_as_float(f2tf32(v));
}

// ---------------- CSR build (adj > 0) ----------------
__global__ void csr_count(const float* __restrict__ adj, int* __restrict__ deg) {
    int w = (blockIdx.x * blockDim.x + threadIdx.x) >> 5;
    int lane = threadIdx.x & 31;
    if (w >= NN_) return;
    const float* row = adj + (size_t)w * NN_;
    int cnt = 0;
    for (int c = 0; c < NN_/32; c++) {
        unsigned m = __ballot_sync(0xffffffffu, row[c*32 + lane] > 0.f);
        cnt += __popc(m);
    }
    if (lane == 0) deg[w] = cnt;
}

__global__ void csr_scan(const int* __restrict__ deg, int* __restrict__ rowptr) {
    __shared__ int ps[128];
    int t = threadIdx.x; // 128
    int s = 0;
    for (int i = 0; i < 16; i++) s += deg[t*16 + i];
    ps[t] = s;
    __syncthreads();
    if (t == 0) { int run = 0; for (int i = 0; i < 128; i++) { int v = ps[i]; ps[i] = run; run += v; } }
    __syncthreads();
    int run = ps[t];
    for (int i = 0; i < 16; i++) { rowptr[t*16 + i] = run; run += deg[t*16 + i]; }
    if (t == 127) rowptr[NN_] = run;
}

__global__ void csr_fill(const float* __restrict__ adj, const int* __restrict__ rowptr,
                         int* __restrict__ colidx) {
    int w = (blockIdx.x * blockDim.x + threadIdx.x) >> 5;
    int lane = threadIdx.x & 31;
    if (w >= NN_) return;
    const float* row = adj + (size_t)w * NN_;
    int base = rowptr[w];
    for (int c = 0; c < NN_/32; c++) {
        int j = c*32 + lane;
        bool p = row[j] > 0.f;
        unsigned m = __ballot_sync(0xffffffffu, p);
        if (p) colidx[base + __popc(m & ((1u << lane) - 1u))] = j;
        base += __popc(m);
    }
}

// ---------------- GAT pieces ----------------
__global__ void gat_scores(const float* __restrict__ Wh, const float* __restrict__ a1,
                           const float* __restrict__ a2, float* __restrict__ s1,
                           float* __restrict__ s2) {
    int n = blockIdx.x;
    int w = threadIdx.x >> 5, lane = threadIdx.x & 31;  // 8 warps = 8 heads
    const float* wr  = Wh + (size_t)n * GH + w * HD;
    const float* a1p = a1 + w * HD;
    const float* a2p = a2 + w * HD;
    float v1 = 0.f, v2 = 0.f;
    for (int o = lane; o < HD; o += 32) { float x = wr[o]; v1 += x * a1p[o]; v2 += x * a2p[o]; }
    #pragma unroll
    for (int o = 16; o; o >>= 1) {
        v1 += __shfl_xor_sync(0xffffffffu, v1, o);
        v2 += __shfl_xor_sync(0xffffffffu, v2, o);
    }
    if (lane == 0) { s1[n*NH + w] = v1; s2[n*NH + w] = v2; }
}

// aggregate + (fused) LayerNorm + ELU + residual-add -> out_x
__global__ void __launch_bounds__(256) gat_aggregate_ln(
    const float* __restrict__ Wh, const float* __restrict__ s1,
    const float* __restrict__ s2, const int* __restrict__ rowptr,
    const int* __restrict__ colidx,
    const float* __restrict__ lng, const float* __restrict__ lnb,
    const float* __restrict__ resid, float* __restrict__ out_x)
{
    const int i = blockIdx.x, tid = threadIdx.x, lane = tid & 31, w = tid >> 5;
    __shared__ float s1sh[8], mh[8], zh[8];
    __shared__ float wred[8][8];
    __shared__ float att[128*8];
    __shared__ int   jsh[128];
    __shared__ float red8[8];

    if (tid < 8) s1sh[tid] = s1[i*NH + tid];
    const int base = rowptr[i];
    const int deg  = rowptr[i+1] - base;
    __syncthreads();

    float lm[8];
    #pragma unroll
    for (int h = 0; h < 8; h++) lm[h] = -1e30f;
    for (int jj = tid; jj < deg; jj += 256) {
        int j = colidx[base + jj];
        #pragma unroll
        for (int h = 0; h < 8; h++) {
            float e = s1sh[h] + s2[j*NH + h];
            e = e > 0.f ? e : 0.2f * e;
            lm[h] = fmaxf(lm[h], e);
        }
    }
    #pragma unroll
    for (int h = 0; h < 8; h++) {
        #pragma unroll
        for (int o = 16; o; o >>= 1) lm[h] = fmaxf(lm[h], __shfl_xor_sync(0xffffffffu, lm[h], o));
    }
    if (lane == 0) {
        for (int h = 0; h < 8; h++) wred[w][h] = lm[h];
    }
    __syncthreads();
    if (tid < 8) {
        float m = wred[0][tid];
        for (int ww = 1; ww < 8; ww++) m = fmaxf(m, wred[ww][tid]);
        mh[tid] = m;
    }
    __syncthreads();

    float ls[8];
    #pragma unroll
    for (int h = 0; h < 8; h++) ls[h] = 0.f;
    for (int jj = tid; jj < deg; jj += 256) {
        int j = colidx[base + jj];
        #pragma unroll
        for (int h = 0; h < 8; h++) {
            float e = s1sh[h] + s2[j*NH + h];
            e = e > 0.f ? e : 0.2f * e;
            ls[h] += expf(e - mh[h]);
        }
    }
    #pragma unroll
    for (int h = 0; h < 8; h++) {
        #pragma unroll
        for (int o = 16; o; o >>= 1) ls[h] += __shfl_xor_sync(0xffffffffu, ls[h], o);
    }
    __syncthreads();
    if (lane == 0) {
        for (int h = 0; h < 8; h++) wred[w][h] = ls[h];
    }
    __syncthreads();
    if (tid < 8) {
        float s = 0.f;
        for (int ww = 0; ww < 8; ww++) s += wred[ww][tid];
        zh[tid] = s;
    }
    __syncthreads();

    float acc0 = 0.f, acc1 = 0.f, acc2 = 0.f, acc3 = 0.f;
    const int c0 = tid, c1 = tid + 256, c2 = tid + 512, c3 = tid + 768;
    const int h0 = c0 >> 7, h1 = c1 >> 7, h2 = c2 >> 7, h3 = c3 >> 7;
    for (int cs = 0; cs < deg; cs += 128) {
        const int nck = min(128, deg - cs);
        __syncthreads();
        for (int idx = tid; idx < nck; idx += 256) jsh[idx] = colidx[base + cs + idx];
        for (int idx = tid; idx < nck * 8; idx += 256) {
            int jj = idx >> 3, h = idx & 7;
            int j = colidx[base + cs + jj];
            float e = s1sh[h] + s2[j*NH + h];
            e = e > 0.f ? e : 0.2f * e;
            att[idx] = expf(e - mh[h]) / zh[h];
        }
        __syncthreads();
        int jj = 0;
        for (; jj + 1 < nck; jj += 2) {
            const float* wr0 = Wh + (size_t)jsh[jj] * GH;
            const float* at0 = att + jj * 8;
            const float* wr1 = Wh + (size_t)jsh[jj+1] * GH;
            const float* at1 = att + (jj+1) * 8;
            acc0 += at0[h0] * wr0[c0] + at1[h0] * wr1[c0];
            acc1 += at0[h1] * wr0[c1] + at1[h1] * wr1[c1];
            acc2 += at0[h2] * wr0[c2] + at1[h2] * wr1[c2];
            acc3 += at0[h3] * wr0[c3] + at1[h3] * wr1[c3];
        }
        if (jj < nck) {
            const float* wr = Wh + (size_t)jsh[jj] * GH;
            const float* at = att + jj * 8;
            acc0 += at[h0] * wr[c0];
            acc1 += at[h1] * wr[c1];
            acc2 += at[h2] * wr[c2];
            acc3 += at[h3] * wr[c3];
        }
    }
    __syncthreads();

    // ---- fused LayerNorm + ELU + residual ----
    float s = acc0 + acc1 + acc2 + acc3;
    s = blk_sum256(s, red8);
    float mu = s * (1.f/1024.f);
    float d0 = acc0 - mu, d1 = acc1 - mu, d2 = acc2 - mu, d3 = acc3 - mu;
    float q = d0*d0 + d1*d1 + d2*d2 + d3*d3;
    q = blk_sum256(q, red8);
    float rstd = rsqrtf(q * (1.f/1024.f) + 1e-5f);
    float* orow = out_x + (size_t)i * GH;
    const float* rrow = resid + (size_t)i * GH;
    {
        float y = d0 * rstd * lng[c0] + lnb[c0];
        float e = y > 0.f ? y : expm1f(y);
        orow[c0] = rrow[c0] + e;
        y = d1 * rstd * lng[c1] + lnb[c1];
        e = y > 0.f ? y : expm1f(y);
        orow[c1] = rrow[c1] + e;
        y = d2 * rstd * lng[c2] + lnb[c2];
        e = y > 0.f ? y : expm1f(y);
        orow[c2] = rrow[c2] + e;
        y = d3 * rstd * lng[c3] + lnb[c3];
        e = y > 0.f ? y : expm1f(y);
        orow[c3] = rrow[c3] + e;
    }
}

// ---------------- LN + gelu (MLP path) ----------------
__global__ void ln_act(const float* __restrict__ X, const float* __restrict__ g,
                       const float* __restrict__ b, float* __restrict__ out) {
    __shared__ float red8[8];
    int row = blockIdx.x, tid = threadIdx.x;
    const float* xr = X + (size_t)row * 1024;
    float v[4];
    #pragma unroll
    for (int k = 0; k < 4; k++) v[k] = xr[tid + 256*k];
    float s = v[0] + v[1] + v[2] + v[3];
    s = blk_sum256(s, red8);
    float mu = s * (1.f/1024.f);
    float q = 0.f;
    #pragma unroll
    for (int k = 0; k < 4; k++) { float d = v[k] - mu; q += d * d; }
    q = blk_sum256(q, red8);
    float rstd = rsqrtf(q * (1.f/1024.f) + 1e-5f);
    float* orow = out + (size_t)row * 1024;
    #pragma unroll
    for (int k = 0; k < 4; k++) {
        int c = tid + 256*k;
        float y = (v[k] - mu) * rstd * g[c] + b[c];
        orow[c] = y * 0.5f * (1.f + erff(y * 0.70710678118654752f));
    }
}

__global__ void l2norm_rows(const float* __restrict__ X, float* __restrict__ out) {
    __shared__ float red8[8];
    int row = blockIdx.x, tid = threadIdx.x;
    const float* xr = X + (size_t)row * 1024;
    float v[4];
    #pragma unroll
    for (int k = 0; k < 4; k++) v[k] = xr[tid + 256*k];
    float q = v[0]*v[0] + v[1]*v[1] + v[2]*v[2] + v[3]*v[3];
    q = blk_sum256(q, red8);
    float inv = 1.f / fmaxf(sqrtf(q), 1e-12f);
    float* orow = out + (size_t)row * 1024;
    #pragma unroll
    for (int k = 0; k < 4; k++) orow[tid + 256*k] = v[k] * inv;
}

__global__ void rowdot(const float* __restrict__ A, const float* __restrict__ B,
                       float* __restrict__ out) {
    __shared__ float red8[8];
    int row = blockIdx.x, tid = threadIdx.x;
    const float* ar = A + (size_t)row * 1024;
    const float* br = B + (size_t)row * 1024;
    float s = 0.f;
    #pragma unroll
    for (int k = 0; k < 4; k++) { int c = tid + 256*k; s += ar[c] * br[c]; }
    s = blk_sum256(s, red8);
    if (tid == 0) out[row] = s;
}

__global__ void lse_rows(const float* __restrict__ neg, float* __restrict__ infoRow) {
    __shared__ float red8[8];
    int row = blockIdx.x, tid = threadIdx.x;
    const float* r = neg + (size_t)row * 1024;
    float v[4];
    #pragma unroll
    for (int k = 0; k < 4; k++) v[k] = r[tid + 256*k] * 20.0f;  // 1/TEMP
    float m = fmaxf(fmaxf(v[0], v[1]), fmaxf(v[2], v[3]));
    m = blk_max256(m, red8);
    float s = 0.f;
    #pragma unroll
    for (int k = 0; k < 4; k++) s += expf(v[k] - m);
    s = blk_sum256(s, red8);
    if (tid == 0) {
        float pos = r[row] * 20.0f;
        float lse = m + logf(expf(pos - m) + s);
        infoRow[row] = lse - pos;
    }
}

__global__ void finalize_k(const float* __restrict__ infoRow, const float* __restrict__ lapRow,
                           float* __restrict__ out, int out_size) {
    __shared__ float ri[32], rl[32];
    int tid = threadIdx.x, lane = tid & 31, w = tid >> 5; // 1024 threads
    float vi = infoRow[tid];
    float vl = lapRow[tid] + lapRow[tid + 1024];
    #pragma unroll
    for (int o = 16; o; o >>= 1) {
        vi += __shfl_xor_sync(0xffffffffu, vi, o);
        vl += __shfl_xor_sync(0xffffffffu, vl, o);
    }
    if (lane == 0) { ri[w] = vi; rl[w] = vl; }
    __syncthreads();
    if (tid == 0) {
        float si = 0.f, sl = 0.f;
        for (int k = 0; k < 32; k++) { si += ri[k]; sl += rl[k]; }
        float info = si / 1024.f;
        float lap  = sl / 2048.f;
        float total = info + 0.1f * lap;
        out[0] = total;
        if (out_size > 1) out[1] = info;
        if (out_size > 2) out[2] = lap;
    }
}

// ---------------- host ----------------
extern "C" void kernel_launch(void* const* d_in, const int* in_sizes, int n_in,
                              void* d_out, int out_size) {
    const float* query = (const float*)d_in[0];
    const float* docs  = (const float*)d_in[1];
    const float* nodes = (const float*)d_in[2];
    const float* adj   = (const float*)d_in[3];
    const float* lapl  = (const float*)d_in[4];
    const float* qW1 = (const float*)d_in[5];  const float* qb1 = (const float*)d_in[6];
    const float* qg  = (const float*)d_in[7];  const float* qbt = (const float*)d_in[8];
    const float* qW2 = (const float*)d_in[9];  const float* qb2 = (const float*)d_in[10];
    const float* dW1 = (const float*)d_in[11]; const float* db1 = (const float*)d_in[12];
    const float* dg  = (const float*)d_in[13]; const float* dbt = (const float*)d_in[14];
    const float* dW2 = (const float*)d_in[15]; const float* db2 = (const float*)d_in[16];
    const float* gatW = (const float*)d_in[17];
    const float* a1   = (const float*)d_in[18];
    const float* a2   = (const float*)d_in[19];
    const float* ln_g = (const float*)d_in[20];
    const float* ln_b = (const float*)d_in[21];
    const float* poW  = (const float*)d_in[22];
    const float* pob  = (const float*)d_in[23];

    void* tp;
    float *px, *pWh, *ps1, *ps2, *pG, *pGr, *pLG;
    float *pt1, *pt2, *pt3, *pt4, *pq, *pp, *pneg, *pinfo, *plap;
    float *pWr, *ppoWr, *plaplr;
    int *pdeg, *prowptr, *pcolidx;
    cudaGetSymbolAddress(&tp, g_x);   px  = (float*)tp;
    cudaGetSymbolAddress(&tp, g_Wh);  pWh = (float*)tp;
    cudaGetSymbolAddress(&tp, g_s1);  ps1 = (float*)tp;
    cudaGetSymbolAddress(&tp, g_s2);  ps2 = (float*)tp;
    cudaGetSymbolAddress(&tp, g_G);   pG  = (float*)tp;
    cudaGetSymbolAddress(&tp, g_Gr);  pGr = (float*)tp;
    cudaGetSymbolAddress(&tp, g_LG);  pLG = (float*)tp;
    cudaGetSymbolAddress(&tp, g_t1);  pt1 = (float*)tp;
    cudaGetSymbolAddress(&tp, g_t2);  pt2 = (float*)tp;
    cudaGetSymbolAddress(&tp, g_t3);  pt3 = (float*)tp;
    cudaGetSymbolAddress(&tp, g_t4);  pt4 = (float*)tp;
    cudaGetSymbolAddress(&tp, g_q);   pq  = (float*)tp;
    cudaGetSymbolAddress(&tp, g_p);   pp  = (float*)tp;
    cudaGetSymbolAddress(&tp, g_neg); pneg = (float*)tp;
    cudaGetSymbolAddress(&tp, g_infoRow); pinfo = (float*)tp;
    cudaGetSymbolAddress(&tp, g_lapRow);  plap  = (float*)tp;
    cudaGetSymbolAddress(&tp, g_Wr);    pWr    = (float*)tp;
    cudaGetSymbolAddress(&tp, g_poWr);  ppoWr  = (float*)tp;
    cudaGetSymbolAddress(&tp, g_laplr); plaplr = (float*)tp;
    cudaGetSymbolAddress(&tp, g_deg);     pdeg    = (int*)tp;
    cudaGetSymbolAddress(&tp, g_rowptr);  prowptr = (int*)tp;
    cudaGetSymbolAddress(&tp, g_colidx);  pcolidx = (int*)tp;

    static cudaStream_t sQ = nullptr, sD = nullptr, sC = nullptr;
    static cudaEvent_t evRoot, evQ, evD, evC, evW0, evW, evSC;
    if (!sQ) {
        cudaStreamCreateWithFlags(&sQ, cudaStreamNonBlocking);
        cudaStreamCreateWithFlags(&sD, cudaStreamNonBlocking);
        cudaStreamCreateWithFlags(&sC, cudaStreamNonBlocking);
        cudaEventCreateWithFlags(&evRoot, cudaEventDisableTiming);
        cudaEventCreateWithFlags(&evQ, cudaEventDisableTiming);
        cudaEventCreateWithFlags(&evD, cudaEventDisableTiming);
        cudaEventCreateWithFlags(&evC, cudaEventDisableTiming);
        cudaEventCreateWithFlags(&evW0, cudaEventDisableTiming);
        cudaEventCreateWithFlags(&evW, cudaEventDisableTiming);
        cudaEventCreateWithFlags(&evSC, cudaEventDisableTiming);
        cudaFuncSetAttribute(gemm_ca<true,true>,  cudaFuncAttributeMaxDynamicSharedMemorySize, GC_SMEM);
        cudaFuncSetAttribute(gemm_ca<true,false>, cudaFuncAttributeMaxDynamicSharedMemorySize, GC_SMEM);
        cudaFuncSetAttribute(gemm_ca<false,false>,cudaFuncAttributeMaxDynamicSharedMemorySize, GC_SMEM);
        cudaFuncSetAttribute(gemm_nt_tf32, cudaFuncAttributeMaxDynamicSharedMemorySize, GSMEM_BYTES);
    }

    // fork point
    cudaEventRecord(evRoot, 0);
    cudaStreamWaitEvent(sQ, evRoot, 0);
    cudaStreamWaitEvent(sD, evRoot, 0);
    cudaStreamWaitEvent(sC, evRoot, 0);

    // ---- stream sC: per-layer gatW reorder+round, CSR, then big rounds; evSC joins all ----
    reorder_gatw_r<<<(ED*GH)/256, 256, 0, sC>>>(gatW, pWr);
    cudaEventRecord(evW0, sC);
    reorder_gatw_r<<<(ED*GH)/256, 256, 0, sC>>>(gatW + (size_t)NH*ED*HD, pWr + (size_t)ED*GH);
    reorder_gatw_r<<<(ED*GH)/256, 256, 0, sC>>>(gatW + (size_t)2*NH*ED*HD, pWr + (size_t)2*ED*GH);
    cudaEventRecord(evW, sC);
    csr_count<<<NN_*32/256, 256, 0, sC>>>(adj, pdeg);
    csr_scan<<<1, 128, 0, sC>>>(pdeg, prowptr);
    csr_fill<<<NN_*32/256, 256, 0, sC>>>(adj, prowptr, pcolidx);
    cudaEventRecord(evC, sC);
    round_f4<<<(GH*ED/4 + 255)/256, 256, 0, sC>>>((const float4*)poW, (float4*)ppoWr, GH*ED/4);
    round_f4<<<(NN_*NN_/4 + 255)/256, 256, 0, sC>>>((const float4*)lapl, (float4*)plaplr, NN_*NN_/4);
    cudaEventRecord(evSC, sC);

    // ---- stream sD: doc MLP -> p ----
    gemm_ca<true,true><<<dim3(ED/128, BB/128), 256, GC_SMEM, sD>>>(docs, dW1, db1, pt3, nullptr, BB, ED, ED);
    ln_act<<<BB, 256, 0, sD>>>(pt3, dg, dbt, pt4);
    gemm_ca<true,true><<<dim3(ED/128, BB/128), 256, GC_SMEM, sD>>>(pt4, dW2, db2, pt3, nullptr, BB, ED, ED);
    l2norm_rows<<<BB, 256, 0, sD>>>(pt3, pp);
    cudaEventRecord(evD, sD);

    // ---- stream sQ: query MLP -> q, then neg + lse ----
    gemm_ca<true,true><<<dim3(ED/128, BB/128), 256, GC_SMEM, sQ>>>(query, qW1, qb1, pt1, nullptr, BB, ED, ED);
    ln_act<<<BB, 256, 0, sQ>>>(pt1, qg, qbt, pt2);
    gemm_ca<true,true><<<dim3(ED/128, BB/128), 256, GC_SMEM, sQ>>>(pt2, qW2, qb2, pt1, nullptr, BB, ED, ED);
    l2norm_rows<<<BB, 256, 0, sQ>>>(pt1, pq);
    cudaStreamWaitEvent(sQ, evD, 0);
    gemm_nt_tf32<<<dim3(BB/128, BB/128), 256, GSMEM_BYTES, sQ>>>(pq, pp, pneg, BB, BB, ED);
    lse_rows<<<BB, 256, 0, sQ>>>(pneg, pinfo);
    cudaEventRecord(evQ, sQ);

    // ---- default stream: GNN chain ----
    cudaStreamWaitEvent(0, evW0, 0);
    for (int l = 0; l < NL; l++) {
        const float* xin = (l == 0) ? nodes : px;
        if (l == 1) cudaStreamWaitEvent(0, evW, 0);
        gemm_ca<true,false><<<dim3(GH/128, NN_/128), 256, GC_SMEM>>>(
            xin, pWr + (size_t)l*ED*GH, nullptr, pWh, nullptr, NN_, GH, ED);
        gat_scores<<<NN_, 256>>>(pWh, a1 + l*NH*HD, a2 + l*NH*HD, ps1, ps2);
        if (l == 0) cudaStreamWaitEvent(0, evC, 0);
        gat_aggregate_ln<<<NN_, 256>>>(pWh, ps1, ps2, prowptr, pcolidx,
                                       ln_g + l*GH, ln_b + l*GH, xin, px);
    }
    // G (fp32, for rowdot) + Gr (tf32-rounded, as B of the laplacian GEMM)
    cudaStreamWaitEvent(0, evSC, 0);
    gemm_ca<true,false><<<dim3(ED/128, NN_/128), 256, GC_SMEM>>>(px, ppoWr, pob, pG, pGr, NN_, ED, GH);
    gemm_ca<false,false><<<dim3(ED/128, NN_/128), 256, GC_SMEM>>>(plaplr, pGr, nullptr, pLG, nullptr, NN_, ED, NN_);
    rowdot<<<NN_, 256>>>(pG, pLG, plap);

    // ---- join + finalize ----
    cudaStreamWaitEvent(0, evQ, 0);
    finalize_k<<<1, 1024>>>(pinfo, plap, (float*)d_out, out_size);
}